// round 3
// baseline (speedup 1.0000x reference)
#include <cuda_runtime.h>

#define BS 128
#define SEQ 2048
#define NV 64
#define DM 512
#define KC 64
#define NROWS (BS*NV)          // 8192
#define MAX_ITER 10
#define TOL 1e-4f
#define PROB_ELEMS (BS*NV*KC)  // 524288
#define CENT_ELEMS (KC*DM)     // 32768

// ---------------- device scratch (no allocations allowed) ----------------
__device__ float g_cent[KC*DM];
__device__ float g_sums[KC*DM];
__device__ int   g_counts[KC];
__device__ float g_centsq[KC];
__device__ float g_xsq[NROWS];
__device__ int   g_ids[NROWS];
__device__ int   g_done;

// ---------------- init: copy centroids, clear done flag ----------------
__global__ void init_k(const float* __restrict__ centroids) {
    int i = blockIdx.x * blockDim.x + threadIdx.x;
    if (i == 0) g_done = 0;
    if (i < KC*DM) g_cent[i] = centroids[i];
}

// ---------------- embedding GEMM ----------------
// x_emb[(b*64+v), d] = sum_s x[b, s, v] * W[d, s] + bias[d]
// Per block: one batch b, one 64-wide d-tile; 64(v) x 64(d) output tile, K=2048.
// 256 threads, 4x4 micro-tiles.
__global__ __launch_bounds__(256) void gemm_k(
    const float* __restrict__ x, const float* __restrict__ W,
    const float* __restrict__ bias, float* __restrict__ xe)
{
    const int b  = blockIdx.y;
    const int d0 = blockIdx.x * 64;
    const int t  = threadIdx.x;
    const int tx = t & 15;       // d group
    const int ty = t >> 4;       // v group

    __shared__ float xs[32][64];   // [s][v]
    __shared__ float ws[32][65];   // [s][d], padded (conflict-free transpose store)

    float acc[4][4] = {};
    const float* xb = x + (size_t)b * SEQ * NV;

    for (int s0 = 0; s0 < SEQ; s0 += 32) {
        // stage x tile: 32 s-rows of 64 contiguous v — float4, coalesced
        {
            const float4* src = (const float4*)(xb + (size_t)s0 * NV);
            float4* dst = (float4*)(&xs[0][0]);
            dst[t]       = src[t];
            dst[t + 256] = src[t + 256];
        }
        // stage W tile with transpose: read coalesced along s, store padded
        #pragma unroll
        for (int j = 0; j < 8; j++) {
            int i  = t + 256 * j;
            int ss = i & 31, dd = i >> 5;
            ws[ss][dd] = W[(size_t)(d0 + dd) * SEQ + s0 + ss];
        }
        __syncthreads();

        #pragma unroll
        for (int s = 0; s < 32; s++) {
            float4 xv = *((const float4*)(&xs[s][0]) + ty);
            float w0 = ws[s][tx*4+0], w1 = ws[s][tx*4+1];
            float w2 = ws[s][tx*4+2], w3 = ws[s][tx*4+3];
            acc[0][0] += xv.x*w0; acc[0][1] += xv.x*w1; acc[0][2] += xv.x*w2; acc[0][3] += xv.x*w3;
            acc[1][0] += xv.y*w0; acc[1][1] += xv.y*w1; acc[1][2] += xv.y*w2; acc[1][3] += xv.y*w3;
            acc[2][0] += xv.z*w0; acc[2][1] += xv.z*w1; acc[2][2] += xv.z*w2; acc[2][3] += xv.z*w3;
            acc[3][0] += xv.w*w0; acc[3][1] += xv.w*w1; acc[3][2] += xv.w*w2; acc[3][3] += xv.w*w3;
        }
        __syncthreads();
    }

    float b0 = bias[d0 + tx*4 + 0];
    float b1 = bias[d0 + tx*4 + 1];
    float b2 = bias[d0 + tx*4 + 2];
    float b3 = bias[d0 + tx*4 + 3];
    #pragma unroll
    for (int j = 0; j < 4; j++) {
        int v = ty*4 + j;
        size_t row = (size_t)b * NV + v;
        float4 o = make_float4(acc[j][0] + b0, acc[j][1] + b1,
                               acc[j][2] + b2, acc[j][3] + b3);
        *(float4*)(xe + row * DM + d0 + tx*4) = o;
    }
}

// ---------------- row squared norms: one warp per row ----------------
__global__ void xsq_k(const float* __restrict__ xe) {
    int warp = (blockIdx.x * blockDim.x + threadIdx.x) >> 5;
    int lane = threadIdx.x & 31;
    if (warp >= NROWS) return;
    const float* r = xe + (size_t)warp * DM;
    float s = 0.f;
    #pragma unroll
    for (int i = 0; i < DM/32; i++) { float v = r[i*32 + lane]; s += v*v; }
    #pragma unroll
    for (int o = 16; o; o >>= 1) s += __shfl_xor_sync(~0u, s, o);
    if (lane == 0) g_xsq[warp] = s;
}

// ---------------- per-iter prep: cent_sq, zero sums/counts ----------------
__global__ void prep_k() {
    if (g_done) return;
    int k = blockIdx.x, t = threadIdx.x;
    float s = 0.f;
    #pragma unroll
    for (int j = 0; j < DM/128; j++) {
        int i = t + j*128;
        float c = g_cent[k*DM + i];
        s += c*c;
        g_sums[k*DM + i] = 0.f;
    }
    __shared__ float red[128];
    red[t] = s; __syncthreads();
    for (int o = 64; o; o >>= 1) { if (t < o) red[t] += red[t+o]; __syncthreads(); }
    if (t == 0) g_centsq[k] = red[0];
    if (k == 0 && t < KC) g_counts[t] = 0;
}

// ---------------- assignment: 4 rows per warp, butterfly-reduced dots ----------------
__global__ __launch_bounds__(256) void assign_k(const float* __restrict__ xe) {
    if (g_done) return;
    int warp = threadIdx.x >> 5, lane = threadIdx.x & 31;
    int n0 = (blockIdx.x * 8 + warp) * 4;

    float xr[4][16];
    #pragma unroll
    for (int r = 0; r < 4; r++)
        #pragma unroll
        for (int i = 0; i < 16; i++)
            xr[r][i] = xe[(size_t)(n0 + r) * DM + i*32 + lane];

    float xsq0 = g_xsq[n0+0], xsq1 = g_xsq[n0+1], xsq2 = g_xsq[n0+2], xsq3 = g_xsq[n0+3];
    float best0 = 3.4e38f, best1 = 3.4e38f, best2 = 3.4e38f, best3 = 3.4e38f;
    int   bid0 = 0, bid1 = 0, bid2 = 0, bid3 = 0;

    for (int k = 0; k < KC; k++) {
        const float* c = g_cent + (size_t)k * DM;
        float p0 = 0.f, p1 = 0.f, p2 = 0.f, p3 = 0.f;
        #pragma unroll
        for (int i = 0; i < 16; i++) {
            float cv = __ldg(&c[i*32 + lane]);
            p0 += xr[0][i]*cv; p1 += xr[1][i]*cv;
            p2 += xr[2][i]*cv; p3 += xr[3][i]*cv;
        }
        #pragma unroll
        for (int o = 16; o; o >>= 1) {
            p0 += __shfl_xor_sync(~0u, p0, o);
            p1 += __shfl_xor_sync(~0u, p1, o);
            p2 += __shfl_xor_sync(~0u, p2, o);
            p3 += __shfl_xor_sync(~0u, p3, o);
        }
        float cs = g_centsq[k];
        float d0 = xsq0 - 2.f*p0 + cs; if (d0 < best0) { best0 = d0; bid0 = k; }
        float d1 = xsq1 - 2.f*p1 + cs; if (d1 < best1) { best1 = d1; bid1 = k; }
        float d2 = xsq2 - 2.f*p2 + cs; if (d2 < best2) { best2 = d2; bid2 = k; }
        float d3 = xsq3 - 2.f*p3 + cs; if (d3 < best3) { best3 = d3; bid3 = k; }
    }
    // all lanes agree after butterfly; lanes 0..3 commit rows n0..n0+3
    int myid = (lane == 0) ? bid0 : (lane == 1) ? bid1 : (lane == 2) ? bid2 : bid3;
    if (lane < 4) {
        g_ids[n0 + lane] = myid;
        atomicAdd(&g_counts[myid], 1);
    }
}

// ---------------- centroid accumulation: smem-staged, then global atomics ----------
// grid (4 d-chunks x 64 row-chunks), 128 threads; block covers dims [dc*128, +128),
// rows [rc*128, +128). smem sums [64 clusters][128 dims].
__global__ __launch_bounds__(128) void accum_k(const float* __restrict__ xe) {
    if (g_done) return;
    __shared__ float s[KC * 128];   // 32 KB
    int t  = threadIdx.x;
    int dc = blockIdx.x;
    int rc = blockIdx.y;
    #pragma unroll
    for (int i = t; i < KC*128; i += 128) s[i] = 0.f;
    __syncthreads();
    int n0 = rc * 128;
    #pragma unroll 4
    for (int n = n0; n < n0 + 128; n++) {
        int id  = g_ids[n];
        float v = xe[(size_t)n * DM + dc*128 + t];
        atomicAdd(&s[id*128 + t], v);   // tid->distinct banks, conflict-free
    }
    __syncthreads();
    for (int k = 0; k < KC; k++)
        atomicAdd(&g_sums[(size_t)k * DM + dc*128 + t], s[k*128 + t]);
}

// ---------------- centroid update + shift norm + done flag ----------------
__global__ void update_k() {
    if (g_done) return;
    int t = threadIdx.x;   // 1024 threads
    float sh = 0.f;
    #pragma unroll
    for (int j = 0; j < (KC*DM)/1024; j++) {
        int e = t + j*1024;
        int k = e >> 9;                       // e / DM
        float cnt  = (float)g_counts[k];
        float old  = g_cent[e];
        float mean = g_sums[e] / fmaxf(cnt, 1.f);
        float nc   = (cnt > 0.f) ? mean : old;
        float d = nc - old;
        sh += d*d;
        g_cent[e] = nc;
    }
    __shared__ float red[1024];
    red[t] = sh; __syncthreads();
    for (int o = 512; o; o >>= 1) { if (t < o) red[t] += red[t+o]; __syncthreads(); }
    if (t == 0 && sqrtf(red[0]) < TOL) g_done = 1;
}

// ---------------- finalize: one-hot prob (by comparison) + cent copy ----------------
__global__ void final_k(float* __restrict__ out) {
    int i = blockIdx.x * blockDim.x + threadIdx.x;
    if (i < PROB_ELEMS) {
        int n = i >> 6, k = i & 63;
        out[i] = (g_ids[n] == k) ? 1.f : 0.f;
    }
    if (i < CENT_ELEMS) out[PROB_ELEMS + i] = g_cent[i];
}

// ---------------- launch ----------------
extern "C" void kernel_launch(void* const* d_in, const int* in_sizes, int n_in,
                              void* d_out, int out_size) {
    const float* x         = (const float*)d_in[0];
    const float* W         = (const float*)d_in[1];
    const float* bias      = (const float*)d_in[2];
    const float* centroids = (const float*)d_in[3];
    float* out = (float*)d_out;
    float* xe  = out + PROB_ELEMS + CENT_ELEMS;   // x_emb written straight to output

    init_k<<<(KC*DM + 255)/256, 256>>>(centroids);
    gemm_k<<<dim3(DM/64, BS), 256>>>(x, W, bias, xe);
    xsq_k<<<(NROWS*32)/256, 256>>>(xe);

    for (int it = 0; it < MAX_ITER; it++) {
        prep_k  <<<KC, 128>>>();
        assign_k<<<NROWS/32, 256>>>(xe);
        accum_k <<<dim3(4, 64), 128>>>(xe);
        update_k<<<1, 1024>>>();
    }
    final_k<<<(PROB_ELEMS + 255)/256, 256>>>(out);
}

// round 5
// speedup vs baseline: 1.1044x; 1.1044x over previous
#include <cuda_runtime.h>

#define BS 128
#define SEQ 2048
#define NV 64
#define DM 512
#define KC 64
#define NROWS (BS*NV)          // 8192
#define MAX_ITER 10
#define TOL 1e-4f
#define PROB_ELEMS (BS*NV*KC)  // 524288
#define CENT_ELEMS (KC*DM)     // 32768

// ---------------- device scratch (no allocations allowed) ----------------
__device__ float g_cent[KC*DM];
__device__ float g_sums[KC*DM];
__device__ int   g_counts[KC];
__device__ float g_centsq[KC];
__device__ float g_xsq[NROWS];
__device__ int   g_ids[NROWS];
__device__ int   g_done;
__device__ float g_shift;

// ---------------- init: copy centroids, zero scratch ----------------
__global__ void init_k(const float* __restrict__ centroids) {
    int i = blockIdx.x * blockDim.x + threadIdx.x;
    if (i == 0) { g_done = 0; g_shift = 0.f; }
    if (i < KC) g_counts[i] = 0;
    if (i < KC*DM) { g_cent[i] = centroids[i]; g_sums[i] = 0.f; }
}

// ---------------- initial centroid squared norms ----------------
__global__ void centsq0_k() {
    int k = blockIdx.x, t = threadIdx.x;   // 128 threads
    float s = 0.f;
    #pragma unroll
    for (int j = 0; j < DM/128; j++) {
        float c = g_cent[k*DM + t + j*128];
        s += c*c;
    }
    __shared__ float r[128];
    r[t] = s; __syncthreads();
    for (int o = 64; o; o >>= 1) { if (t < o) r[t] += r[t+o]; __syncthreads(); }
    if (t == 0) g_centsq[k] = r[0];
}

// ---------------- embedding GEMM: 128x128x16, 8x8 micro-tile ----------------
// x_emb[n, d] = sum_s x[b, s, v] * W[d, s] + bias[d],  n = b*64 + v
// Block: 128 n-rows x 128 d-cols. 256 threads, each computes 8x8.
__global__ __launch_bounds__(256) void gemm_k(
    const float* __restrict__ x, const float* __restrict__ W,
    const float* __restrict__ bias, float* __restrict__ xe)
{
    __shared__ float As[16][128];       // [s][n]
    __shared__ float Bs[16][132];       // [s][d], pad 4 -> 132 (528B rows, 16B aligned)

    const int t  = threadIdx.x;
    const int n0 = blockIdx.y * 128;
    const int d0 = blockIdx.x * 128;
    const int tn = t & 15;              // n micro-group
    const int td = t >> 4;              // d micro-group

    // A-load mapping: thread loads 2 float4 along n at s rows (as, as+8)
    const int an4 = t & 31;             // float4 index along n
    const int as  = t >> 5;             // 0..7
    const int n_g = n0 + an4 * 4;
    const int ab  = n_g >> 6;           // batch
    const int av  = n_g & 63;           // var (float4-aligned, no b crossing)
    const float* xA = x + (size_t)ab * SEQ * NV + av;

    // B-load mapping: thread loads 2 float4 along s for one d row
    const int bd  = t >> 1;             // 0..127
    const int bs0 = (t & 1) * 8;        // 0 or 8
    const float* wB = W + (size_t)(d0 + bd) * SEQ + bs0;

    float acc[8][8] = {};

    for (int s0 = 0; s0 < SEQ; s0 += 16) {
        float4 a0g = *(const float4*)(xA + (size_t)(s0 + as)     * NV);
        float4 a1g = *(const float4*)(xA + (size_t)(s0 + as + 8) * NV);
        float4 b0g = *(const float4*)(wB + s0);
        float4 b1g = *(const float4*)(wB + s0 + 4);

        *(float4*)&As[as][an4*4]     = a0g;
        *(float4*)&As[as+8][an4*4]   = a1g;
        Bs[bs0+0][bd] = b0g.x; Bs[bs0+1][bd] = b0g.y;
        Bs[bs0+2][bd] = b0g.z; Bs[bs0+3][bd] = b0g.w;
        Bs[bs0+4][bd] = b1g.x; Bs[bs0+5][bd] = b1g.y;
        Bs[bs0+6][bd] = b1g.z; Bs[bs0+7][bd] = b1g.w;
        __syncthreads();

        #pragma unroll
        for (int s = 0; s < 16; s++) {
            float4 a0 = *(const float4*)&As[s][tn*4];
            float4 a1 = *(const float4*)&As[s][tn*4 + 64];
            float4 b0 = *(const float4*)&Bs[s][td*4];
            float4 b1 = *(const float4*)&Bs[s][td*4 + 64];
            float an[8] = {a0.x, a0.y, a0.z, a0.w, a1.x, a1.y, a1.z, a1.w};
            float bn[8] = {b0.x, b0.y, b0.z, b0.w, b1.x, b1.y, b1.z, b1.w};
            #pragma unroll
            for (int i = 0; i < 8; i++)
                #pragma unroll
                for (int j = 0; j < 8; j++)
                    acc[i][j] += an[i] * bn[j];
        }
        __syncthreads();
    }

    float bi[8];
    #pragma unroll
    for (int j = 0; j < 8; j++)
        bi[j] = bias[d0 + (j < 4 ? td*4 + j : 64 + td*4 + j - 4)];

    #pragma unroll
    for (int i = 0; i < 8; i++) {
        int n = n0 + (i < 4 ? tn*4 + i : 64 + tn*4 + i - 4);
        float4 o0 = make_float4(acc[i][0]+bi[0], acc[i][1]+bi[1],
                                acc[i][2]+bi[2], acc[i][3]+bi[3]);
        float4 o1 = make_float4(acc[i][4]+bi[4], acc[i][5]+bi[5],
                                acc[i][6]+bi[6], acc[i][7]+bi[7]);
        *(float4*)(xe + (size_t)n * DM + d0 + td*4)      = o0;
        *(float4*)(xe + (size_t)n * DM + d0 + 64 + td*4) = o1;
    }
}

// ---------------- row squared norms: one warp per row ----------------
__global__ void xsq_k(const float* __restrict__ xe) {
    int warp = (blockIdx.x * blockDim.x + threadIdx.x) >> 5;
    int lane = threadIdx.x & 31;
    if (warp >= NROWS) return;
    const float* r = xe + (size_t)warp * DM;
    float s = 0.f;
    #pragma unroll
    for (int i = 0; i < DM/32; i++) { float v = r[i*32 + lane]; s += v*v; }
    #pragma unroll
    for (int o = 16; o; o >>= 1) s += __shfl_xor_sync(~0u, s, o);
    if (lane == 0) g_xsq[warp] = s;
}

// ---------------- assignment: 4 rows per warp, butterfly-reduced dots ----------------
__global__ __launch_bounds__(256) void assign_k(const float* __restrict__ xe) {
    if (g_done) return;
    int warp = threadIdx.x >> 5, lane = threadIdx.x & 31;
    int n0 = (blockIdx.x * 8 + warp) * 4;

    float xr[4][16];
    #pragma unroll
    for (int r = 0; r < 4; r++)
        #pragma unroll
        for (int i = 0; i < 16; i++)
            xr[r][i] = xe[(size_t)(n0 + r) * DM + i*32 + lane];

    float xsq0 = g_xsq[n0+0], xsq1 = g_xsq[n0+1], xsq2 = g_xsq[n0+2], xsq3 = g_xsq[n0+3];
    float best0 = 3.4e38f, best1 = 3.4e38f, best2 = 3.4e38f, best3 = 3.4e38f;
    int   bid0 = 0, bid1 = 0, bid2 = 0, bid3 = 0;

    for (int k = 0; k < KC; k++) {
        const float* c = g_cent + (size_t)k * DM;
        float p0 = 0.f, p1 = 0.f, p2 = 0.f, p3 = 0.f;
        #pragma unroll
        for (int i = 0; i < 16; i++) {
            float cv = __ldg(&c[i*32 + lane]);
            p0 += xr[0][i]*cv; p1 += xr[1][i]*cv;
            p2 += xr[2][i]*cv; p3 += xr[3][i]*cv;
        }
        #pragma unroll
        for (int o = 16; o; o >>= 1) {
            p0 += __shfl_xor_sync(~0u, p0, o);
            p1 += __shfl_xor_sync(~0u, p1, o);
            p2 += __shfl_xor_sync(~0u, p2, o);
            p3 += __shfl_xor_sync(~0u, p3, o);
        }
        float cs = g_centsq[k];
        float d0 = xsq0 - 2.f*p0 + cs; if (d0 < best0) { best0 = d0; bid0 = k; }
        float d1 = xsq1 - 2.f*p1 + cs; if (d1 < best1) { best1 = d1; bid1 = k; }
        float d2 = xsq2 - 2.f*p2 + cs; if (d2 < best2) { best2 = d2; bid2 = k; }
        float d3 = xsq3 - 2.f*p3 + cs; if (d3 < best3) { best3 = d3; bid3 = k; }
    }
    int myid = (lane == 0) ? bid0 : (lane == 1) ? bid1 : (lane == 2) ? bid2 : bid3;
    if (lane < 4) {
        g_ids[n0 + lane] = myid;
        atomicAdd(&g_counts[myid], 1);
    }
}

// ---------------- centroid accumulation: smem-staged, then global atomics ----------
__global__ __launch_bounds__(128) void accum_k(const float* __restrict__ xe) {
    if (g_done) return;
    __shared__ float s[KC * 128];   // 32 KB
    int t  = threadIdx.x;
    int dc = blockIdx.x;
    int rc = blockIdx.y;
    #pragma unroll
    for (int i = t; i < KC*128; i += 128) s[i] = 0.f;
    __syncthreads();
    int n0 = rc * 128;
    #pragma unroll 4
    for (int n = n0; n < n0 + 128; n++) {
        int id  = g_ids[n];
        float v = xe[(size_t)n * DM + dc*128 + t];
        atomicAdd(&s[id*128 + t], v);
    }
    __syncthreads();
    for (int k = 0; k < KC; k++)
        atomicAdd(&g_sums[(size_t)k * DM + dc*128 + t], s[k*128 + t]);
}

// ---------------- centroid update (per-cluster block): new cent, centsq,
//                  zero sums/counts, partial shift norm ----------------
__global__ void update_k() {
    if (g_done) return;
    int k = blockIdx.x, t = threadIdx.x;   // 64 blocks x 128 threads
    float cnt = (float)g_counts[k];
    float inv = 1.f / fmaxf(cnt, 1.f);
    bool  has = cnt > 0.f;
    float sh = 0.f, cs = 0.f;
    #pragma unroll
    for (int j = 0; j < DM/128; j++) {
        int e = k*DM + t + j*128;
        float old = g_cent[e];
        float nc  = has ? g_sums[e] * inv : old;
        g_cent[e] = nc;
        g_sums[e] = 0.f;
        float d = nc - old;
        sh += d*d;
        cs += nc*nc;
    }
    __shared__ float r1[128], r2[128];
    r1[t] = sh; r2[t] = cs; __syncthreads();
    for (int o = 64; o; o >>= 1) {
        if (t < o) { r1[t] += r1[t+o]; r2[t] += r2[t+o]; }
        __syncthreads();
    }
    if (t == 0) {
        g_centsq[k] = r2[0];
        atomicAdd(&g_shift, r1[0]);
        g_counts[k] = 0;
    }
}

// ---------------- done check ----------------
__global__ void done_k() {
    if (!g_done && sqrtf(g_shift) < TOL) g_done = 1;
    g_shift = 0.f;
}

// ---------------- finalize: one-hot prob + cent copy ----------------
__global__ void final_k(float* __restrict__ out) {
    int i = blockIdx.x * blockDim.x + threadIdx.x;
    if (i < PROB_ELEMS) {
        int n = i >> 6, k = i & 63;
        out[i] = (g_ids[n] == k) ? 1.f : 0.f;
    }
    if (i < CENT_ELEMS) out[PROB_ELEMS + i] = g_cent[i];
}

// ---------------- launch ----------------
extern "C" void kernel_launch(void* const* d_in, const int* in_sizes, int n_in,
                              void* d_out, int out_size) {
    const float* x         = (const float*)d_in[0];
    const float* W         = (const float*)d_in[1];
    const float* bias      = (const float*)d_in[2];
    const float* centroids = (const float*)d_in[3];
    float* out = (float*)d_out;
    float* xe  = out + PROB_ELEMS + CENT_ELEMS;   // x_emb written straight to output

    init_k<<<(KC*DM + 255)/256, 256>>>(centroids);
    gemm_k<<<dim3(DM/128, NROWS/128), 256>>>(x, W, bias, xe);
    xsq_k<<<(NROWS*32)/256, 256>>>(xe);
    centsq0_k<<<KC, 128>>>();

    for (int it = 0; it < MAX_ITER; it++) {
        assign_k<<<NROWS/32, 256>>>(xe);
        accum_k <<<dim3(4, 64), 128>>>(xe);
        update_k<<<KC, 128>>>();
        done_k  <<<1, 1>>>();
    }
    final_k<<<(PROB_ELEMS + 255)/256, 256>>>(out);
}

// round 6
// speedup vs baseline: 1.1985x; 1.0852x over previous
#include <cuda_runtime.h>

#define BS 128
#define SEQ 2048
#define NV 64
#define DM 512
#define KC 64
#define NROWS (BS*NV)          // 8192
#define MAX_ITER 10
#define TOL 1e-4f
#define PROB_ELEMS (BS*NV*KC)  // 524288
#define CENT_ELEMS (KC*DM)     // 32768

typedef unsigned long long u64;

// packed fp32x2 helpers (sm_103a FFMA2 path — exact fp32 semantics per lane)
__device__ __forceinline__ u64 pk2(float x) {
    u64 r; asm("mov.b64 %0, {%1, %1};" : "=l"(r) : "f"(x)); return r;
}
__device__ __forceinline__ void fma2(u64& d, u64 a, u64 b) {
    asm("fma.rn.f32x2 %0, %1, %2, %3;" : "=l"(d) : "l"(a), "l"(b), "l"(d));
}
__device__ __forceinline__ float2 upk(u64 v) {
    float2 f; asm("mov.b64 {%0, %1}, %2;" : "=f"(f.x), "=f"(f.y) : "l"(v)); return f;
}

// ---------------- device scratch (no allocations allowed) ----------------
__device__ float g_cent[KC*DM];
__device__ float g_sums[KC*DM];
__device__ int   g_counts[KC];
__device__ float g_centsq[KC];
__device__ float g_xsq[NROWS];
__device__ int   g_ids[NROWS];
__device__ int   g_done;
__device__ float g_shift;

// ---------------- init: copy centroids, zero scratch ----------------
__global__ void init_k(const float* __restrict__ centroids) {
    int i = blockIdx.x * blockDim.x + threadIdx.x;
    if (i == 0) { g_done = 0; g_shift = 0.f; }
    if (i < KC) g_counts[i] = 0;
    if (i < KC*DM) { g_cent[i] = centroids[i]; g_sums[i] = 0.f; }
}

// ---------------- initial centroid squared norms ----------------
__global__ void centsq0_k() {
    int k = blockIdx.x, t = threadIdx.x;   // 128 threads
    float s = 0.f;
    #pragma unroll
    for (int j = 0; j < DM/128; j++) {
        float c = g_cent[k*DM + t + j*128];
        s += c*c;
    }
    __shared__ float r[128];
    r[t] = s; __syncthreads();
    for (int o = 64; o; o >>= 1) { if (t < o) r[t] += r[t+o]; __syncthreads(); }
    if (t == 0) g_centsq[k] = r[0];
}

// ---------------- embedding GEMM: 128x128x16, 8x8 micro-tile, FFMA2 + double buffer --
// x_emb[n, d] = sum_s x[b, s, v] * W[d, s] + bias[d],  n = b*64 + v
__global__ __launch_bounds__(256, 2) void gemm_k(
    const float* __restrict__ x, const float* __restrict__ W,
    const float* __restrict__ bias, float* __restrict__ xe)
{
    __shared__ float As[2][16][128];    // [buf][s][n]
    __shared__ float Bs[2][16][132];    // [buf][s][d], pad 4 (528B rows, 16B aligned)

    const int t  = threadIdx.x;
    const int n0 = blockIdx.y * 128;
    const int d0 = blockIdx.x * 128;
    const int tn = t & 15;              // n micro-group
    const int td = t >> 4;              // d micro-group

    // A-load mapping: thread loads 2 float4 along n at s rows (as, as+8)
    const int an4 = t & 31;
    const int as  = t >> 5;
    const int n_g = n0 + an4 * 4;
    const float* xA = x + (size_t)(n_g >> 6) * SEQ * NV + (n_g & 63);

    // B-load mapping: thread loads 2 float4 along s for one d row
    const int bd  = t >> 1;
    const int bs0 = (t & 1) * 8;
    const float* wB = W + (size_t)(d0 + bd) * SEQ + bs0;

    u64 acc[8][4] = {};                 // packed f32x2 accumulators (8 n x 4 d-pairs)

    // prefetch chunk 0
    float4 a0g = *(const float4*)(xA + (size_t)as * NV);
    float4 a1g = *(const float4*)(xA + (size_t)(as + 8) * NV);
    float4 b0g = *(const float4*)(wB);
    float4 b1g = *(const float4*)(wB + 4);

    // stage chunk 0
    *(float4*)&As[0][as][an4*4]   = a0g;
    *(float4*)&As[0][as+8][an4*4] = a1g;
    Bs[0][bs0+0][bd] = b0g.x; Bs[0][bs0+1][bd] = b0g.y;
    Bs[0][bs0+2][bd] = b0g.z; Bs[0][bs0+3][bd] = b0g.w;
    Bs[0][bs0+4][bd] = b1g.x; Bs[0][bs0+5][bd] = b1g.y;
    Bs[0][bs0+6][bd] = b1g.z; Bs[0][bs0+7][bd] = b1g.w;
    __syncthreads();

    int buf = 0;
    for (int s0 = 0; s0 < SEQ; s0 += 16) {
        const bool more = (s0 + 16) < SEQ;
        if (more) {   // prefetch next chunk into registers (overlaps compute)
            a0g = *(const float4*)(xA + (size_t)(s0 + 16 + as)     * NV);
            a1g = *(const float4*)(xA + (size_t)(s0 + 16 + as + 8) * NV);
            b0g = *(const float4*)(wB + s0 + 16);
            b1g = *(const float4*)(wB + s0 + 20);
        }

        #pragma unroll
        for (int s = 0; s < 16; s++) {
            float4 a0 = *(const float4*)&As[buf][s][tn*4];
            float4 a1 = *(const float4*)&As[buf][s][tn*4 + 64];
            ulonglong2 bq0 = *(const ulonglong2*)&Bs[buf][s][td*4];       // pairs (d0..d3)
            ulonglong2 bq1 = *(const ulonglong2*)&Bs[buf][s][td*4 + 64];  // pairs (d64..d67)
            float av[8] = {a0.x, a0.y, a0.z, a0.w, a1.x, a1.y, a1.z, a1.w};
            #pragma unroll
            for (int i = 0; i < 8; i++) {
                u64 ap = pk2(av[i]);
                fma2(acc[i][0], ap, bq0.x);
                fma2(acc[i][1], ap, bq0.y);
                fma2(acc[i][2], ap, bq1.x);
                fma2(acc[i][3], ap, bq1.y);
            }
        }

        if (more) {
            int nb = buf ^ 1;
            *(float4*)&As[nb][as][an4*4]   = a0g;
            *(float4*)&As[nb][as+8][an4*4] = a1g;
            Bs[nb][bs0+0][bd] = b0g.x; Bs[nb][bs0+1][bd] = b0g.y;
            Bs[nb][bs0+2][bd] = b0g.z; Bs[nb][bs0+3][bd] = b0g.w;
            Bs[nb][bs0+4][bd] = b1g.x; Bs[nb][bs0+5][bd] = b1g.y;
            Bs[nb][bs0+6][bd] = b1g.z; Bs[nb][bs0+7][bd] = b1g.w;
            __syncthreads();
            buf = nb;
        }
    }

    float bi[8];
    #pragma unroll
    for (int j = 0; j < 8; j++)
        bi[j] = bias[d0 + (j < 4 ? td*4 + j : 64 + td*4 + j - 4)];

    #pragma unroll
    for (int i = 0; i < 8; i++) {
        int n = n0 + (i < 4 ? tn*4 + i : 64 + tn*4 + i - 4);
        float2 p0 = upk(acc[i][0]), p1 = upk(acc[i][1]);
        float2 p2 = upk(acc[i][2]), p3 = upk(acc[i][3]);
        float4 o0 = make_float4(p0.x + bi[0], p0.y + bi[1], p1.x + bi[2], p1.y + bi[3]);
        float4 o1 = make_float4(p2.x + bi[4], p2.y + bi[5], p3.x + bi[6], p3.y + bi[7]);
        *(float4*)(xe + (size_t)n * DM + d0 + td*4)      = o0;
        *(float4*)(xe + (size_t)n * DM + d0 + 64 + td*4) = o1;
    }
}

// ---------------- row squared norms: one warp per row ----------------
__global__ void xsq_k(const float* __restrict__ xe) {
    int warp = (blockIdx.x * blockDim.x + threadIdx.x) >> 5;
    int lane = threadIdx.x & 31;
    if (warp >= NROWS) return;
    const float* r = xe + (size_t)warp * DM;
    float s = 0.f;
    #pragma unroll
    for (int i = 0; i < DM/32; i++) { float v = r[i*32 + lane]; s += v*v; }
    #pragma unroll
    for (int o = 16; o; o >>= 1) s += __shfl_xor_sync(~0u, s, o);
    if (lane == 0) g_xsq[warp] = s;
}

// ---------------- assignment: 4 rows per warp, butterfly-reduced dots ----------------
__global__ __launch_bounds__(256) void assign_k(const float* __restrict__ xe) {
    if (g_done) return;
    int warp = threadIdx.x >> 5, lane = threadIdx.x & 31;
    int n0 = (blockIdx.x * 8 + warp) * 4;

    float xr[4][16];
    #pragma unroll
    for (int r = 0; r < 4; r++)
        #pragma unroll
        for (int i = 0; i < 16; i++)
            xr[r][i] = xe[(size_t)(n0 + r) * DM + i*32 + lane];

    float xsq0 = g_xsq[n0+0], xsq1 = g_xsq[n0+1], xsq2 = g_xsq[n0+2], xsq3 = g_xsq[n0+3];
    float best0 = 3.4e38f, best1 = 3.4e38f, best2 = 3.4e38f, best3 = 3.4e38f;
    int   bid0 = 0, bid1 = 0, bid2 = 0, bid3 = 0;

    for (int k = 0; k < KC; k++) {
        const float* c = g_cent + (size_t)k * DM;
        float p0 = 0.f, p1 = 0.f, p2 = 0.f, p3 = 0.f;
        #pragma unroll
        for (int i = 0; i < 16; i++) {
            float cv = __ldg(&c[i*32 + lane]);
            p0 += xr[0][i]*cv; p1 += xr[1][i]*cv;
            p2 += xr[2][i]*cv; p3 += xr[3][i]*cv;
        }
        #pragma unroll
        for (int o = 16; o; o >>= 1) {
            p0 += __shfl_xor_sync(~0u, p0, o);
            p1 += __shfl_xor_sync(~0u, p1, o);
            p2 += __shfl_xor_sync(~0u, p2, o);
            p3 += __shfl_xor_sync(~0u, p3, o);
        }
        float cs = g_centsq[k];
        float d0 = xsq0 - 2.f*p0 + cs; if (d0 < best0) { best0 = d0; bid0 = k; }
        float d1 = xsq1 - 2.f*p1 + cs; if (d1 < best1) { best1 = d1; bid1 = k; }
        float d2 = xsq2 - 2.f*p2 + cs; if (d2 < best2) { best2 = d2; bid2 = k; }
        float d3 = xsq3 - 2.f*p3 + cs; if (d3 < best3) { best3 = d3; bid3 = k; }
    }
    int myid = (lane == 0) ? bid0 : (lane == 1) ? bid1 : (lane == 2) ? bid2 : bid3;
    if (lane < 4) {
        g_ids[n0 + lane] = myid;
        atomicAdd(&g_counts[myid], 1);
    }
}

// ---------------- centroid accumulation: smem-staged, then global atomics ----------
__global__ __launch_bounds__(128) void accum_k(const float* __restrict__ xe) {
    if (g_done) return;
    __shared__ float s[KC * 128];   // 32 KB
    int t  = threadIdx.x;
    int dc = blockIdx.x;
    int rc = blockIdx.y;
    #pragma unroll
    for (int i = t; i < KC*128; i += 128) s[i] = 0.f;
    __syncthreads();
    int n0 = rc * 128;
    #pragma unroll 4
    for (int n = n0; n < n0 + 128; n++) {
        int id  = g_ids[n];
        float v = xe[(size_t)n * DM + dc*128 + t];
        atomicAdd(&s[id*128 + t], v);
    }
    __syncthreads();
    for (int k = 0; k < KC; k++)
        atomicAdd(&g_sums[(size_t)k * DM + dc*128 + t], s[k*128 + t]);
}

// ---------------- centroid update (per-cluster block) ----------------
__global__ void update_k() {
    if (g_done) return;
    int k = blockIdx.x, t = threadIdx.x;   // 64 blocks x 128 threads
    float cnt = (float)g_counts[k];
    float inv = 1.f / fmaxf(cnt, 1.f);
    bool  has = cnt > 0.f;
    float sh = 0.f, cs = 0.f;
    #pragma unroll
    for (int j = 0; j < DM/128; j++) {
        int e = k*DM + t + j*128;
        float old = g_cent[e];
        float nc  = has ? g_sums[e] * inv : old;
        g_cent[e] = nc;
        g_sums[e] = 0.f;
        float d = nc - old;
        sh += d*d;
        cs += nc*nc;
    }
    __shared__ float r1[128], r2[128];
    r1[t] = sh; r2[t] = cs; __syncthreads();
    for (int o = 64; o; o >>= 1) {
        if (t < o) { r1[t] += r1[t+o]; r2[t] += r2[t+o]; }
        __syncthreads();
    }
    if (t == 0) {
        g_centsq[k] = r2[0];
        atomicAdd(&g_shift, r1[0]);
        g_counts[k] = 0;
    }
}

// ---------------- done check ----------------
__global__ void done_k() {
    if (!g_done && sqrtf(g_shift) < TOL) g_done = 1;
    g_shift = 0.f;
}

// ---------------- finalize: one-hot prob + cent copy ----------------
__global__ void final_k(float* __restrict__ out) {
    int i = blockIdx.x * blockDim.x + threadIdx.x;
    if (i < PROB_ELEMS) {
        int n = i >> 6, k = i & 63;
        out[i] = (g_ids[n] == k) ? 1.f : 0.f;
    }
    if (i < CENT_ELEMS) out[PROB_ELEMS + i] = g_cent[i];
}

// ---------------- launch ----------------
extern "C" void kernel_launch(void* const* d_in, const int* in_sizes, int n_in,
                              void* d_out, int out_size) {
    const float* x         = (const float*)d_in[0];
    const float* W         = (const float*)d_in[1];
    const float* bias      = (const float*)d_in[2];
    const float* centroids = (const float*)d_in[3];
    float* out = (float*)d_out;
    float* xe  = out + PROB_ELEMS + CENT_ELEMS;   // x_emb written straight to output

    init_k<<<(KC*DM + 255)/256, 256>>>(centroids);
    gemm_k<<<dim3(DM/128, NROWS/128), 256>>>(x, W, bias, xe);
    xsq_k<<<(NROWS*32)/256, 256>>>(xe);
    centsq0_k<<<KC, 128>>>();

    for (int it = 0; it < MAX_ITER; it++) {
        assign_k<<<NROWS/32, 256>>>(xe);
        accum_k <<<dim3(4, 64), 128>>>(xe);
        update_k<<<KC, 128>>>();
        done_k  <<<1, 1>>>();
    }
    final_k<<<(PROB_ELEMS + 255)/256, 256>>>(out);
}

// round 10
// speedup vs baseline: 1.3561x; 1.1315x over previous
#include <cuda_runtime.h>
#include <cuda_bf16.h>
#include <cstdint>

#define BS 128
#define SEQ 2048
#define NV 64
#define DM 512
#define KC 64
#define NROWS (BS*NV)          // 8192
#define MAX_ITER 10
#define TOL 1e-4f
#define PROB_ELEMS (BS*NV*KC)  // 524288
#define CENT_ELEMS (KC*DM)     // 32768

// ================= baseline-PTX helpers (family-safe, no 'a' features) =====
__device__ __forceinline__ uint32_t smem_u32(const void* p) {
    uint32_t a;
    asm("{ .reg .u64 t; cvta.to.shared.u64 t, %1; cvt.u32.u64 %0, t; }" : "=r"(a) : "l"(p));
    return a;
}
__device__ __forceinline__ void cpasync16(uint32_t s, const void* g) {
    asm volatile("cp.async.ca.shared.global [%0], [%1], 16;" :: "r"(s), "l"(g));
}
#define CP_COMMIT()  asm volatile("cp.async.commit_group;" ::: "memory")
#define CP_WAIT(n)   asm volatile("cp.async.wait_group %0;" :: "n"(n) : "memory")

__device__ __forceinline__ void ldsm4(uint32_t& r0, uint32_t& r1, uint32_t& r2, uint32_t& r3,
                                      uint32_t addr) {
    asm volatile("ldmatrix.sync.aligned.m8n8.x4.shared.b16 {%0,%1,%2,%3}, [%4];"
        : "=r"(r0), "=r"(r1), "=r"(r2), "=r"(r3) : "r"(addr));
}
__device__ __forceinline__ void mma16816(float* c, const uint32_t* a, const uint32_t* b) {
    asm volatile("mma.sync.aligned.m16n8k16.row.col.f32.bf16.bf16.f32 "
        "{%0,%1,%2,%3}, {%4,%5,%6,%7}, {%8,%9}, {%0,%1,%2,%3};"
        : "+f"(c[0]), "+f"(c[1]), "+f"(c[2]), "+f"(c[3])
        : "r"(a[0]), "r"(a[1]), "r"(a[2]), "r"(a[3]), "r"(b[0]), "r"(b[1]));
}

// ================= device scratch =================
__device__ float g_cent[KC*DM];
__device__ float g_sums[KC*DM];
__device__ int   g_counts[KC];
__device__ float g_centsq[KC];
__device__ float g_xsq[NROWS];
__device__ int   g_ids[NROWS];
__device__ int   g_done;
__device__ float g_shift;
// bf16 split matrices: A = x transposed to [n][s], B = W [d][s]
__device__ __nv_bfloat16 g_Ah[NROWS*SEQ];
__device__ __nv_bfloat16 g_Al[NROWS*SEQ];
__device__ __nv_bfloat16 g_Wh[DM*SEQ];
__device__ __nv_bfloat16 g_Wl[DM*SEQ];

// ================= init =================
__global__ void init_k(const float* __restrict__ centroids) {
    int i = blockIdx.x * blockDim.x + threadIdx.x;
    if (i == 0) { g_done = 0; g_shift = 0.f; }
    if (i < KC) g_counts[i] = 0;
    if (i < KC*DM) { g_cent[i] = centroids[i]; g_sums[i] = 0.f; }
}

__global__ void centsq0_k() {
    int k = blockIdx.x, t = threadIdx.x;
    float s = 0.f;
    #pragma unroll
    for (int j = 0; j < DM/128; j++) {
        float c = g_cent[k*DM + t + j*128];
        s += c*c;
    }
    __shared__ float r[128];
    r[t] = s; __syncthreads();
    for (int o = 64; o; o >>= 1) { if (t < o) r[t] += r[t+o]; __syncthreads(); }
    if (t == 0) g_centsq[k] = r[0];
}

// ================= bf16 split kernels =================
union BPack { __nv_bfloat16 h[8]; uint4 u; };

// W [DM][SEQ] -> Wh/Wl same layout. 8 elems per thread.
__global__ __launch_bounds__(256) void splitw_k(const float* __restrict__ W) {
    int i = (blockIdx.x * 256 + threadIdx.x) * 8;
    BPack ph, pl;
    #pragma unroll
    for (int j = 0; j < 8; j++) {
        float f = W[i + j];
        __nv_bfloat16 h = __float2bfloat16(f);
        ph.h[j] = h;
        pl.h[j] = __float2bfloat16(f - __bfloat162float(h));
    }
    *(uint4*)&g_Wh[i] = ph.u;
    *(uint4*)&g_Wl[i] = pl.u;
}

// x [BS][SEQ][NV] -> A[n = b*64+v][s], split hi/lo. Transpose via smem tile.
__global__ __launch_bounds__(256) void splitx_k(const float* __restrict__ x) {
    __shared__ float xs[64][65];
    int b  = blockIdx.x;
    int s0 = blockIdx.y * 64;
    int t  = threadIdx.x;
    const float* xp = x + ((size_t)b * SEQ + s0) * NV;
    int v = t & 63, i0 = t >> 6;
    #pragma unroll
    for (int j = 0; j < 16; j++)
        xs[i0 + j*4][v] = xp[(size_t)(i0 + j*4) * NV + v];
    __syncthreads();
    #pragma unroll
    for (int kx = 0; kx < 2; kx++) {
        int w = t + kx * 256;
        int v2 = w >> 3, seg = w & 7;
        BPack ph, pl;
        #pragma unroll
        for (int j = 0; j < 8; j++) {
            float f = xs[seg*8 + j][v2];
            __nv_bfloat16 h = __float2bfloat16(f);
            ph.h[j] = h;
            pl.h[j] = __float2bfloat16(f - __bfloat162float(h));
        }
        size_t off = (size_t)(b*64 + v2) * SEQ + s0 + seg*8;
        *(uint4*)&g_Ah[off] = ph.u;
        *(uint4*)&g_Al[off] = pl.u;
    }
}

// ================= HMMA GEMM (mma.sync bf16x3, cp.async double-buffered) ====
// xe[n][d] = sum_s A[n][s]*B[d][s] + bias[d], via Ah*Bh + Al*Bh + Ah*Bl
// Block 128(n) x 128(d); 8 warps (2x4); warp tile 64x32; K-chunk 32.
#define ASTRIDE 80                     // 32 bf16 (64B) + 16B pad: conflict-free
#define TILE_B  (128*ASTRIDE)          // 10240 B per matrix tile
#define BUF_B   (4*TILE_B)             // Ah, Al, Bh, Bl
#define SM_GEMM (2*BUF_B)              // 81920 B double-buffered

__global__ __launch_bounds__(256, 2) void mma_gemm_k(
    const float* __restrict__ bias, float* __restrict__ xe)
{
    extern __shared__ char smem[];
    const uint32_t sb = smem_u32(smem);
    const int t = threadIdx.x;
    const int wid = t >> 5, lane = t & 31;
    const int n0 = blockIdx.y * 128, d0 = blockIdx.x * 128;
    const int wm = wid >> 2, wn = wid & 3;      // 2 x 4 warp grid

    const __nv_bfloat16* gm[4] = {
        g_Ah + (size_t)n0 * SEQ, g_Al + (size_t)n0 * SEQ,
        g_Wh + (size_t)d0 * SEQ, g_Wl + (size_t)d0 * SEQ };

    float acc[4][4][4] = {};                    // [mf][nf][4]

    // ldmatrix base addresses (per warp, lane-dependent), without buffer/ks offsets
    // A: row = wm*64 + mf*16 + (lane&15); +16B if lane>=16 (k-half)
    const uint32_t aoff = (uint32_t)(wm*64 + (lane & 15)) * ASTRIDE + (lane >> 4) * 16;
    // B: group = lane>>3: nsel = (group>>1), khalf = group&1, col = lane&7
    const uint32_t boff = (uint32_t)(wn*32 + ((lane >> 4) << 3) + (lane & 7)) * ASTRIDE
                        + (((lane >> 3) & 1) * 16);

    // staging: 512 16B-units per matrix tile; thread does units t, t+256 per matrix
    auto stage = [&](int ch, int buf) {
        const int s0 = ch * 32;
        const uint32_t bb = sb + buf * BUF_B;
        #pragma unroll
        for (int m = 0; m < 4; m++) {
            const __nv_bfloat16* g = gm[m];
            const uint32_t sm = bb + m * TILE_B;
            int r0 = t >> 2,        c0 = t & 3;
            int r1 = (t+256) >> 2,  c1 = (t+256) & 3;
            cpasync16(sm + r0*ASTRIDE + c0*16, g + (size_t)r0 * SEQ + s0 + c0*8);
            cpasync16(sm + r1*ASTRIDE + c1*16, g + (size_t)r1 * SEQ + s0 + c1*8);
        }
        CP_COMMIT();
    };

    stage(0, 0);
    for (int ch = 0; ch < SEQ/32; ch++) {
        const int buf = ch & 1;
        const bool more = (ch + 1) < SEQ/32;
        if (more) { stage(ch + 1, buf ^ 1); CP_WAIT(1); }
        else      { CP_WAIT(0); }
        __syncthreads();

        const uint32_t bb = sb + buf * BUF_B;
        #pragma unroll
        for (int ks = 0; ks < 2; ks++) {
            const uint32_t ko = ks * 32;
            uint32_t Ah[4][4], Al[4][4], Bh[2][4], Bl[2][4];
            // pass 1: hh
            #pragma unroll
            for (int mf = 0; mf < 4; mf++)
                ldsm4(Ah[mf][0], Ah[mf][1], Ah[mf][2], Ah[mf][3],
                      bb + 0*TILE_B + aoff + mf*16*ASTRIDE + ko);
            #pragma unroll
            for (int p = 0; p < 2; p++)
                ldsm4(Bh[p][0], Bh[p][1], Bh[p][2], Bh[p][3],
                      bb + 2*TILE_B + boff + p*16*ASTRIDE + ko);
            #pragma unroll
            for (int mf = 0; mf < 4; mf++)
                #pragma unroll
                for (int nf = 0; nf < 4; nf++)
                    mma16816(acc[mf][nf], Ah[mf], &Bh[nf>>1][(nf&1)*2]);
            // pass 2: lh (Al x Bh)
            #pragma unroll
            for (int mf = 0; mf < 4; mf++)
                ldsm4(Al[mf][0], Al[mf][1], Al[mf][2], Al[mf][3],
                      bb + 1*TILE_B + aoff + mf*16*ASTRIDE + ko);
            #pragma unroll
            for (int mf = 0; mf < 4; mf++)
                #pragma unroll
                for (int nf = 0; nf < 4; nf++)
                    mma16816(acc[mf][nf], Al[mf], &Bh[nf>>1][(nf&1)*2]);
            // pass 3: hl (Ah x Bl)
            #pragma unroll
            for (int p = 0; p < 2; p++)
                ldsm4(Bl[p][0], Bl[p][1], Bl[p][2], Bl[p][3],
                      bb + 3*TILE_B + boff + p*16*ASTRIDE + ko);
            #pragma unroll
            for (int mf = 0; mf < 4; mf++)
                #pragma unroll
                for (int nf = 0; nf < 4; nf++)
                    mma16816(acc[mf][nf], Ah[mf], &Bl[nf>>1][(nf&1)*2]);
        }
        __syncthreads();
    }

    // epilogue: frag layout -> xe (+bias)
    const int tg = lane >> 2, tq = lane & 3;
    #pragma unroll
    for (int mf = 0; mf < 4; mf++) {
        const int r0 = n0 + wm*64 + mf*16 + tg;
        #pragma unroll
        for (int nf = 0; nf < 4; nf++) {
            const int c0 = d0 + wn*32 + nf*8 + tq*2;
            const float2 bv = *(const float2*)(bias + c0);
            float2 o0 = make_float2(acc[mf][nf][0] + bv.x, acc[mf][nf][1] + bv.y);
            float2 o1 = make_float2(acc[mf][nf][2] + bv.x, acc[mf][nf][3] + bv.y);
            *(float2*)(xe + (size_t)r0      * DM + c0) = o0;
            *(float2*)(xe + (size_t)(r0+8)  * DM + c0) = o1;
        }
    }
}

// ================= row squared norms =================
__global__ void xsq_k(const float* __restrict__ xe) {
    int warp = (blockIdx.x * blockDim.x + threadIdx.x) >> 5;
    int lane = threadIdx.x & 31;
    if (warp >= NROWS) return;
    const float* r = xe + (size_t)warp * DM;
    float s = 0.f;
    #pragma unroll
    for (int i = 0; i < DM/32; i++) { float v = r[i*32 + lane]; s += v*v; }
    #pragma unroll
    for (int o = 16; o; o >>= 1) s += __shfl_xor_sync(~0u, s, o);
    if (lane == 0) g_xsq[warp] = s;
}

// ================= assignment =================
__global__ __launch_bounds__(256) void assign_k(const float* __restrict__ xe) {
    if (g_done) return;
    int warp = threadIdx.x >> 5, lane = threadIdx.x & 31;
    int n0 = (blockIdx.x * 8 + warp) * 4;

    float xr[4][16];
    #pragma unroll
    for (int r = 0; r < 4; r++)
        #pragma unroll
        for (int i = 0; i < 16; i++)
            xr[r][i] = xe[(size_t)(n0 + r) * DM + i*32 + lane];

    float xsq0 = g_xsq[n0+0], xsq1 = g_xsq[n0+1], xsq2 = g_xsq[n0+2], xsq3 = g_xsq[n0+3];
    float best0 = 3.4e38f, best1 = 3.4e38f, best2 = 3.4e38f, best3 = 3.4e38f;
    int   bid0 = 0, bid1 = 0, bid2 = 0, bid3 = 0;

    for (int k = 0; k < KC; k++) {
        const float* c = g_cent + (size_t)k * DM;
        float p0 = 0.f, p1 = 0.f, p2 = 0.f, p3 = 0.f;
        #pragma unroll
        for (int i = 0; i < 16; i++) {
            float cv = __ldg(&c[i*32 + lane]);
            p0 += xr[0][i]*cv; p1 += xr[1][i]*cv;
            p2 += xr[2][i]*cv; p3 += xr[3][i]*cv;
        }
        #pragma unroll
        for (int o = 16; o; o >>= 1) {
            p0 += __shfl_xor_sync(~0u, p0, o);
            p1 += __shfl_xor_sync(~0u, p1, o);
            p2 += __shfl_xor_sync(~0u, p2, o);
            p3 += __shfl_xor_sync(~0u, p3, o);
        }
        float cs = g_centsq[k];
        float d0 = xsq0 - 2.f*p0 + cs; if (d0 < best0) { best0 = d0; bid0 = k; }
        float d1 = xsq1 - 2.f*p1 + cs; if (d1 < best1) { best1 = d1; bid1 = k; }
        float d2 = xsq2 - 2.f*p2 + cs; if (d2 < best2) { best2 = d2; bid2 = k; }
        float d3 = xsq3 - 2.f*p3 + cs; if (d3 < best3) { best3 = d3; bid3 = k; }
    }
    int myid = (lane == 0) ? bid0 : (lane == 1) ? bid1 : (lane == 2) ? bid2 : bid3;
    if (lane < 4) {
        g_ids[n0 + lane] = myid;
        atomicAdd(&g_counts[myid], 1);
    }
}

// ================= centroid accumulation =================
__global__ __launch_bounds__(128) void accum_k(const float* __restrict__ xe) {
    if (g_done) return;
    __shared__ float s[KC * 128];   // 32 KB
    int t  = threadIdx.x;
    int dc = blockIdx.x;
    int rc = blockIdx.y;
    #pragma unroll
    for (int i = t; i < KC*128; i += 128) s[i] = 0.f;
    __syncthreads();
    int n0 = rc * 128;
    #pragma unroll 4
    for (int n = n0; n < n0 + 128; n++) {
        int id  = g_ids[n];
        float v = xe[(size_t)n * DM + dc*128 + t];
        atomicAdd(&s[id*128 + t], v);
    }
    __syncthreads();
    for (int k = 0; k < KC; k++)
        atomicAdd(&g_sums[(size_t)k * DM + dc*128 + t], s[k*128 + t]);
}

// ================= centroid update =================
__global__ void update_k() {
    if (g_done) return;
    int k = blockIdx.x, t = threadIdx.x;   // 64 x 128
    float cnt = (float)g_counts[k];
    float inv = 1.f / fmaxf(cnt, 1.f);
    bool  has = cnt > 0.f;
    float sh = 0.f, cs = 0.f;
    #pragma unroll
    for (int j = 0; j < DM/128; j++) {
        int e = k*DM + t + j*128;
        float old = g_cent[e];
        float nc  = has ? g_sums[e] * inv : old;
        g_cent[e] = nc;
        g_sums[e] = 0.f;
        float d = nc - old;
        sh += d*d;
        cs += nc*nc;
    }
    __shared__ float r1[128], r2[128];
    r1[t] = sh; r2[t] = cs; __syncthreads();
    for (int o = 64; o; o >>= 1) {
        if (t < o) { r1[t] += r1[t+o]; r2[t] += r2[t+o]; }
        __syncthreads();
    }
    if (t == 0) {
        g_centsq[k] = r2[0];
        atomicAdd(&g_shift, r1[0]);
        g_counts[k] = 0;
    }
}

__global__ void done_k() {
    if (!g_done && sqrtf(g_shift) < TOL) g_done = 1;
    g_shift = 0.f;
}

// ================= finalize =================
__global__ void final_k(float* __restrict__ out) {
    int i = blockIdx.x * blockDim.x + threadIdx.x;
    if (i < PROB_ELEMS) {
        int n = i >> 6, k = i & 63;
        out[i] = (g_ids[n] == k) ? 1.f : 0.f;
    }
    if (i < CENT_ELEMS) out[PROB_ELEMS + i] = g_cent[i];
}

// ================= launch =================
extern "C" void kernel_launch(void* const* d_in, const int* in_sizes, int n_in,
                              void* d_out, int out_size) {
    const float* x         = (const float*)d_in[0];
    const float* W         = (const float*)d_in[1];
    const float* bias      = (const float*)d_in[2];
    const float* centroids = (const float*)d_in[3];
    float* out = (float*)d_out;
    float* xe  = out + PROB_ELEMS + CENT_ELEMS;   // x_emb written straight to output

    cudaFuncSetAttribute(mma_gemm_k, cudaFuncAttributeMaxDynamicSharedMemorySize, SM_GEMM);

    init_k<<<(KC*DM + 255)/256, 256>>>(centroids);
    splitw_k<<<(DM*SEQ)/(256*8), 256>>>(W);
    splitx_k<<<dim3(BS, SEQ/64), 256>>>(x);
    mma_gemm_k<<<dim3(DM/128, NROWS/128), 256, SM_GEMM>>>(bias, xe);
    xsq_k<<<(NROWS*32)/256, 256>>>(xe);
    centsq0_k<<<KC, 128>>>();

    for (int it = 0; it < MAX_ITER; it++) {
        assign_k<<<NROWS/32, 256>>>(xe);
        accum_k <<<dim3(4, 64), 128>>>(xe);
        update_k<<<KC, 128>>>();
        done_k  <<<1, 1>>>();
    }
    final_k<<<(PROB_ELEMS + 255)/256, 256>>>(out);
}

// round 11
// speedup vs baseline: 2.0382x; 1.5030x over previous
#include <cuda_runtime.h>
#include <cuda_bf16.h>
#include <cstdint>

#define BS 128
#define SEQ 2048
#define NV 64
#define DM 512
#define KC 64
#define NROWS (BS*NV)          // 8192
#define MAX_ITER 10
#define TOL 1e-4f
#define PROB_ELEMS (BS*NV*KC)  // 524288
#define CENT_ELEMS (KC*DM)     // 32768
#define NB 128                 // persistent-kernel blocks (<= 148 SMs, 1 CTA/SM)

typedef unsigned long long u64;

// ================= baseline-PTX helpers (family-safe) =====
__device__ __forceinline__ uint32_t smem_u32(const void* p) {
    uint32_t a;
    asm("{ .reg .u64 t; cvta.to.shared.u64 t, %1; cvt.u32.u64 %0, t; }" : "=r"(a) : "l"(p));
    return a;
}
__device__ __forceinline__ void cpasync16(uint32_t s, const void* g) {
    asm volatile("cp.async.ca.shared.global [%0], [%1], 16;" :: "r"(s), "l"(g));
}
#define CP_COMMIT()  asm volatile("cp.async.commit_group;" ::: "memory")
#define CP_WAIT(n)   asm volatile("cp.async.wait_group %0;" :: "n"(n) : "memory")

__device__ __forceinline__ void ldsm4(uint32_t& r0, uint32_t& r1, uint32_t& r2, uint32_t& r3,
                                      uint32_t addr) {
    asm volatile("ldmatrix.sync.aligned.m8n8.x4.shared.b16 {%0,%1,%2,%3}, [%4];"
        : "=r"(r0), "=r"(r1), "=r"(r2), "=r"(r3) : "r"(addr));
}
__device__ __forceinline__ void mma16816(float* c, const uint32_t* a, const uint32_t* b) {
    asm volatile("mma.sync.aligned.m16n8k16.row.col.f32.bf16.bf16.f32 "
        "{%0,%1,%2,%3}, {%4,%5,%6,%7}, {%8,%9}, {%0,%1,%2,%3};"
        : "+f"(c[0]), "+f"(c[1]), "+f"(c[2]), "+f"(c[3])
        : "r"(a[0]), "r"(a[1]), "r"(a[2]), "r"(a[3]), "r"(b[0]), "r"(b[1]));
}
// packed fp32x2 (exact per-lane fp32)
__device__ __forceinline__ u64 pk2(float x) {
    u64 r; asm("mov.b64 %0, {%1, %1};" : "=l"(r) : "f"(x)); return r;
}
__device__ __forceinline__ void fma2(u64& d, u64 a, u64 b) {
    asm("fma.rn.f32x2 %0, %1, %2, %3;" : "=l"(d) : "l"(a), "l"(b), "l"(d));
}
__device__ __forceinline__ float2 upk(u64 v) {
    float2 f; asm("mov.b64 {%0, %1}, %2;" : "=f"(f.x), "=f"(f.y) : "l"(v)); return f;
}

// ================= device scratch =================
__device__ float g_cent[KC*DM];
__device__ float g_sums[KC*DM];
__device__ int   g_counts[KC];
__device__ float g_centsq[KC];
__device__ float g_xsq[NROWS];
__device__ int   g_ids[NROWS];
__device__ int   g_done;
__device__ float g_shift;
__device__ int   g_cnt;      // grid barrier arrive counter
__device__ int   g_gen;      // grid barrier generation
__device__ int   g_ucnt;     // update-phase completion counter
// bf16 split matrices: A = x transposed to [n][s], B = W [d][s]
__device__ __nv_bfloat16 g_Ah[NROWS*SEQ];
__device__ __nv_bfloat16 g_Al[NROWS*SEQ];
__device__ __nv_bfloat16 g_Wh[DM*SEQ];
__device__ __nv_bfloat16 g_Wl[DM*SEQ];

// ================= init =================
__global__ void init_k(const float* __restrict__ centroids) {
    int i = blockIdx.x * blockDim.x + threadIdx.x;
    if (i == 0) { g_done = 0; g_shift = 0.f; g_cnt = 0; g_gen = 0; g_ucnt = 0; }
    if (i < KC) g_counts[i] = 0;
    if (i < KC*DM) { g_cent[i] = centroids[i]; g_sums[i] = 0.f; }
}

// ================= bf16 split kernels =================
union BPack { __nv_bfloat16 h[8]; uint4 u; };

__global__ __launch_bounds__(256) void splitw_k(const float* __restrict__ W) {
    int i = (blockIdx.x * 256 + threadIdx.x) * 8;
    BPack ph, pl;
    #pragma unroll
    for (int j = 0; j < 8; j++) {
        float f = W[i + j];
        __nv_bfloat16 h = __float2bfloat16(f);
        ph.h[j] = h;
        pl.h[j] = __float2bfloat16(f - __bfloat162float(h));
    }
    *(uint4*)&g_Wh[i] = ph.u;
    *(uint4*)&g_Wl[i] = pl.u;
}

__global__ __launch_bounds__(256) void splitx_k(const float* __restrict__ x) {
    __shared__ float xs[64][65];
    int b  = blockIdx.x;
    int s0 = blockIdx.y * 64;
    int t  = threadIdx.x;
    const float* xp = x + ((size_t)b * SEQ + s0) * NV;
    int v = t & 63, i0 = t >> 6;
    #pragma unroll
    for (int j = 0; j < 16; j++)
        xs[i0 + j*4][v] = xp[(size_t)(i0 + j*4) * NV + v];
    __syncthreads();
    #pragma unroll
    for (int kx = 0; kx < 2; kx++) {
        int w = t + kx * 256;
        int v2 = w >> 3, seg = w & 7;
        BPack ph, pl;
        #pragma unroll
        for (int j = 0; j < 8; j++) {
            float f = xs[seg*8 + j][v2];
            __nv_bfloat16 h = __float2bfloat16(f);
            ph.h[j] = h;
            pl.h[j] = __float2bfloat16(f - __bfloat162float(h));
        }
        size_t off = (size_t)(b*64 + v2) * SEQ + s0 + seg*8;
        *(uint4*)&g_Ah[off] = ph.u;
        *(uint4*)&g_Al[off] = pl.u;
    }
}

// ================= HMMA GEMM (unchanged from R10: 156us, tensor 55%) ====
#define ASTRIDE 80
#define TILE_B  (128*ASTRIDE)
#define BUF_B   (4*TILE_B)
#define SM_GEMM (2*BUF_B)

__global__ __launch_bounds__(256, 2) void mma_gemm_k(
    const float* __restrict__ bias, float* __restrict__ xe)
{
    extern __shared__ char smem[];
    const uint32_t sb = smem_u32(smem);
    const int t = threadIdx.x;
    const int wid = t >> 5, lane = t & 31;
    const int n0 = blockIdx.y * 128, d0 = blockIdx.x * 128;
    const int wm = wid >> 2, wn = wid & 3;

    const __nv_bfloat16* gm[4] = {
        g_Ah + (size_t)n0 * SEQ, g_Al + (size_t)n0 * SEQ,
        g_Wh + (size_t)d0 * SEQ, g_Wl + (size_t)d0 * SEQ };

    float acc[4][4][4] = {};

    const uint32_t aoff = (uint32_t)(wm*64 + (lane & 15)) * ASTRIDE + (lane >> 4) * 16;
    const uint32_t boff = (uint32_t)(wn*32 + ((lane >> 4) << 3) + (lane & 7)) * ASTRIDE
                        + (((lane >> 3) & 1) * 16);

    auto stage = [&](int ch, int buf) {
        const int s0 = ch * 32;
        const uint32_t bb = sb + buf * BUF_B;
        #pragma unroll
        for (int m = 0; m < 4; m++) {
            const __nv_bfloat16* g = gm[m];
            const uint32_t sm = bb + m * TILE_B;
            int r0 = t >> 2,        c0 = t & 3;
            int r1 = (t+256) >> 2,  c1 = (t+256) & 3;
            cpasync16(sm + r0*ASTRIDE + c0*16, g + (size_t)r0 * SEQ + s0 + c0*8);
            cpasync16(sm + r1*ASTRIDE + c1*16, g + (size_t)r1 * SEQ + s0 + c1*8);
        }
        CP_COMMIT();
    };

    stage(0, 0);
    for (int ch = 0; ch < SEQ/32; ch++) {
        const int buf = ch & 1;
        const bool more = (ch + 1) < SEQ/32;
        if (more) { stage(ch + 1, buf ^ 1); CP_WAIT(1); }
        else      { CP_WAIT(0); }
        __syncthreads();

        const uint32_t bb = sb + buf * BUF_B;
        #pragma unroll
        for (int ks = 0; ks < 2; ks++) {
            const uint32_t ko = ks * 32;
            uint32_t Ah[4][4], Al[4][4], Bh[2][4], Bl[2][4];
            #pragma unroll
            for (int mf = 0; mf < 4; mf++)
                ldsm4(Ah[mf][0], Ah[mf][1], Ah[mf][2], Ah[mf][3],
                      bb + 0*TILE_B + aoff + mf*16*ASTRIDE + ko);
            #pragma unroll
            for (int p = 0; p < 2; p++)
                ldsm4(Bh[p][0], Bh[p][1], Bh[p][2], Bh[p][3],
                      bb + 2*TILE_B + boff + p*16*ASTRIDE + ko);
            #pragma unroll
            for (int mf = 0; mf < 4; mf++)
                #pragma unroll
                for (int nf = 0; nf < 4; nf++)
                    mma16816(acc[mf][nf], Ah[mf], &Bh[nf>>1][(nf&1)*2]);
            #pragma unroll
            for (int mf = 0; mf < 4; mf++)
                ldsm4(Al[mf][0], Al[mf][1], Al[mf][2], Al[mf][3],
                      bb + 1*TILE_B + aoff + mf*16*ASTRIDE + ko);
            #pragma unroll
            for (int mf = 0; mf < 4; mf++)
                #pragma unroll
                for (int nf = 0; nf < 4; nf++)
                    mma16816(acc[mf][nf], Al[mf], &Bh[nf>>1][(nf&1)*2]);
            #pragma unroll
            for (int p = 0; p < 2; p++)
                ldsm4(Bl[p][0], Bl[p][1], Bl[p][2], Bl[p][3],
                      bb + 3*TILE_B + boff + p*16*ASTRIDE + ko);
            #pragma unroll
            for (int mf = 0; mf < 4; mf++)
                #pragma unroll
                for (int nf = 0; nf < 4; nf++)
                    mma16816(acc[mf][nf], Ah[mf], &Bl[nf>>1][(nf&1)*2]);
        }
        __syncthreads();
    }

    const int tg = lane >> 2, tq = lane & 3;
    #pragma unroll
    for (int mf = 0; mf < 4; mf++) {
        const int r0 = n0 + wm*64 + mf*16 + tg;
        #pragma unroll
        for (int nf = 0; nf < 4; nf++) {
            const int c0 = d0 + wn*32 + nf*8 + tq*2;
            const float2 bv = *(const float2*)(bias + c0);
            float2 o0 = make_float2(acc[mf][nf][0] + bv.x, acc[mf][nf][1] + bv.y);
            float2 o1 = make_float2(acc[mf][nf][2] + bv.x, acc[mf][nf][3] + bv.y);
            *(float2*)(xe + (size_t)r0      * DM + c0) = o0;
            *(float2*)(xe + (size_t)(r0+8)  * DM + c0) = o1;
        }
    }
}

// ================= persistent k-means kernel =================
// 128 blocks x 256 threads, all co-resident. Software grid barrier.
__device__ __forceinline__ void gridbar() {
    __syncthreads();
    if (threadIdx.x == 0) {
        __threadfence();
        int gen = atomicAdd(&g_gen, 0);
        if (atomicAdd(&g_cnt, 1) == NB - 1) {
            atomicExch(&g_cnt, 0);
            __threadfence();
            atomicAdd(&g_gen, 1);
        } else {
            while (atomicAdd(&g_gen, 0) == gen) { }
        }
    }
    __syncthreads();
    __threadfence();   // gpu-scope: orders + invalidates L1 (CCTL.IVALL)
}

__global__ __launch_bounds__(256, 1) void kmeans_k(
    const float* __restrict__ xe, float* __restrict__ out)
{
    __shared__ float pool[KC * 128];            // 32 KB, reused per phase
    const int t   = threadIdx.x;
    const int blk = blockIdx.x;
    const int n0  = blk * 64;                   // this block's 64 rows

    // ---- pre-phase: xsq (own rows) + centsq (blocks<64) ----
    {
        int row4 = t >> 2, part = t & 3;        // 4 threads per row
        const float* xr = xe + (size_t)(n0 + row4) * DM + part * 128;
        float s = 0.f;
        #pragma unroll
        for (int q = 0; q < 32; q++) {
            float4 v = *(const float4*)(xr + q*4);
            s += v.x*v.x + v.y*v.y + v.z*v.z + v.w*v.w;
        }
        s += __shfl_xor_sync(~0u, s, 1);
        s += __shfl_xor_sync(~0u, s, 2);
        if (part == 0) g_xsq[n0 + row4] = s;

        if (blk < KC) {
            float c1 = __ldcg(&g_cent[blk*DM + t]);
            float c2 = __ldcg(&g_cent[blk*DM + 256 + t]);
            pool[t] = c1*c1 + c2*c2;
            __syncthreads();
            for (int o = 128; o; o >>= 1) { if (t < o) pool[t] += pool[t+o]; __syncthreads(); }
            if (t == 0) g_centsq[blk] = pool[0];
        }
    }
    gridbar();

    const int tn = t & 15, td = t >> 4;

    for (int it = 0; it < MAX_ITER; it++) {
        const int done = __ldcg(&g_done);

        // ---------- PHASE A: assign (64 rows x 64 clusters GEMM, f32x2) ----------
        if (!done) {
            float* xs = pool;                   // [32][68] as xs[s*68 + row]
            float* cs = pool + 32*68;           // [32][68] as cs[s*68 + k]
            u64 acc2[4][2] = {};
            for (int c0 = 0; c0 < DM; c0 += 32) {
                #pragma unroll
                for (int j = 0; j < 2; j++) {
                    int idx = t + j*256;
                    int row = idx >> 3, q = idx & 7;
                    float4 v = *(const float4*)(xe + (size_t)(n0+row)*DM + c0 + q*4);
                    float4 w = __ldcg((const float4*)(g_cent + row*DM + c0 + q*4));
                    xs[(q*4+0)*68 + row] = v.x; xs[(q*4+1)*68 + row] = v.y;
                    xs[(q*4+2)*68 + row] = v.z; xs[(q*4+3)*68 + row] = v.w;
                    cs[(q*4+0)*68 + row] = w.x; cs[(q*4+1)*68 + row] = w.y;
                    cs[(q*4+2)*68 + row] = w.z; cs[(q*4+3)*68 + row] = w.w;
                }
                __syncthreads();
                #pragma unroll
                for (int s = 0; s < 32; s++) {
                    float4 a = *(const float4*)&xs[s*68 + tn*4];
                    ulonglong2 b = *(const ulonglong2*)&cs[s*68 + td*4];
                    float av[4] = {a.x, a.y, a.z, a.w};
                    #pragma unroll
                    for (int i = 0; i < 4; i++) {
                        u64 ap = pk2(av[i]);
                        fma2(acc2[i][0], ap, b.x);
                        fma2(acc2[i][1], ap, b.y);
                    }
                }
                __syncthreads();
            }
            // distances into smem, then first-index argmin scan
            float xq[4], cq[4];
            #pragma unroll
            for (int i = 0; i < 4; i++) xq[i] = g_xsq[n0 + tn*4 + i];
            #pragma unroll
            for (int j = 0; j < 4; j++) cq[j] = __ldcg(&g_centsq[td*4 + j]);
            float* ds = pool;                   // [64][68]
            #pragma unroll
            for (int i = 0; i < 4; i++) {
                float2 p0 = upk(acc2[i][0]), p1 = upk(acc2[i][1]);
                float b = xq[i];
                ds[(tn*4+i)*68 + td*4+0] = b - 2.f*p0.x + cq[0];
                ds[(tn*4+i)*68 + td*4+1] = b - 2.f*p0.y + cq[1];
                ds[(tn*4+i)*68 + td*4+2] = b - 2.f*p1.x + cq[2];
                ds[(tn*4+i)*68 + td*4+3] = b - 2.f*p1.y + cq[3];
            }
            __syncthreads();
            if (t < 64) {
                float best = 3.4e38f; int bid = 0;
                #pragma unroll 8
                for (int k = 0; k < KC; k++) {
                    float v = ds[t*68 + k];
                    if (v < best) { best = v; bid = k; }
                }
                g_ids[n0 + t] = bid;
            }
            __syncthreads();
        }
        gridbar();

        // ---------- PHASE B: accumulate sums/counts ----------
        if (!done) {
            const int dc = blk & 3;             // 128-dim chunk
            const int rc = blk >> 2;            // 256-row chunk (32 chunks)
            const int half = t >> 7, d = t & 127;
            #pragma unroll
            for (int i = t; i < KC*128; i += 256) pool[i] = 0.f;
            __syncthreads();
            const int ra = rc * 256 + half * 128;
            #pragma unroll 4
            for (int i = 0; i < 128; i++) {
                int n = ra + i;
                int id = __ldcg(&g_ids[n]);
                float v = xe[(size_t)n * DM + dc*128 + d];
                atomicAdd(&pool[id*128 + d], v);
            }
            __syncthreads();
            #pragma unroll
            for (int i = t; i < KC*128; i += 256) {
                int k = i >> 7, dd = i & 127;
                atomicAdd(&g_sums[k*DM + dc*128 + dd], pool[i]);
            }
            if (dc == 0) {
                int n = rc*256 + t;
                atomicAdd(&g_counts[__ldcg(&g_ids[n])], 1);
            }
        }
        gridbar();

        // ---------- PHASE C: centroid update + done check ----------
        if (!done && blk < KC) {
            const int k = blk;
            float cnt = (float)__ldcg(&g_counts[k]);
            float inv = 1.f / fmaxf(cnt, 1.f);
            bool  has = cnt > 0.f;
            float sh = 0.f, cq = 0.f;
            #pragma unroll
            for (int j = 0; j < 2; j++) {
                int e = k*DM + t + j*256;
                float old = g_cent[e];          // own-block writes: L1-coherent
                float nc  = has ? __ldcg(&g_sums[e]) * inv : old;
                g_cent[e] = nc;
                g_sums[e] = 0.f;
                float dd = nc - old;
                sh += dd*dd;
                cq += nc*nc;
            }
            pool[t] = sh; pool[256 + t] = cq;
            __syncthreads();
            for (int o = 128; o; o >>= 1) {
                if (t < o) { pool[t] += pool[t+o]; pool[256+t] += pool[256+t+o]; }
                __syncthreads();
            }
            if (t == 0) {
                g_centsq[k] = pool[256];
                atomicAdd(&g_shift, pool[0]);
                g_counts[k] = 0;
                __threadfence();
                if (atomicAdd(&g_ucnt, 1) == KC - 1) {
                    float tot = atomicAdd(&g_shift, 0.f);
                    if (sqrtf(tot) < TOL) g_done = 1;
                    g_shift = 0.f;
                    atomicExch(&g_ucnt, 0);
                }
            }
        }
        gridbar();
    }

    // ---------- finalize: prob one-hot + cent copy ----------
    for (int i = t; i < 1024; i += 256) {       // 64 rows x 16 float4
        int row = i >> 4, kq = (i & 15) << 2;
        int id = __ldcg(&g_ids[n0 + row]);
        float4 o = make_float4(kq+0 == id ? 1.f : 0.f, kq+1 == id ? 1.f : 0.f,
                               kq+2 == id ? 1.f : 0.f, kq+3 == id ? 1.f : 0.f);
        *(float4*)(out + (size_t)(n0+row)*KC + kq) = o;
    }
    if (blk < KC) {
        #pragma unroll
        for (int i = t; i < 128; i += 256) {
            float4 c = __ldcg((const float4*)(g_cent + blk*DM + i*4));
            *(float4*)(out + PROB_ELEMS + blk*DM + i*4) = c;
        }
    }
}

// ================= launch =================
extern "C" void kernel_launch(void* const* d_in, const int* in_sizes, int n_in,
                              void* d_out, int out_size) {
    const float* x         = (const float*)d_in[0];
    const float* W         = (const float*)d_in[1];
    const float* bias      = (const float*)d_in[2];
    const float* centroids = (const float*)d_in[3];
    float* out = (float*)d_out;
    float* xe  = out + PROB_ELEMS + CENT_ELEMS;   // x_emb written straight to output

    cudaFuncSetAttribute(mma_gemm_k, cudaFuncAttributeMaxDynamicSharedMemorySize, SM_GEMM);

    init_k<<<(KC*DM + 255)/256, 256>>>(centroids);
    splitw_k<<<(DM*SEQ)/(256*8), 256>>>(W);
    splitx_k<<<dim3(BS, SEQ/64), 256>>>(x);
    mma_gemm_k<<<dim3(DM/128, NROWS/128), 256, SM_GEMM>>>(bias, xe);
    kmeans_k<<<NB, 256>>>(xe, out);
}

// round 13
// speedup vs baseline: 2.2536x; 1.1057x over previous
#include <cuda_runtime.h>
#include <cuda_bf16.h>
#include <cstdint>

#define BS 128
#define SEQ 2048
#define NV 64
#define DM 512
#define KC 64
#define NROWS (BS*NV)          // 8192
#define MAX_ITER 10
#define TOL 1e-4f
#define PROB_ELEMS (BS*NV*KC)  // 524288
#define CENT_ELEMS (KC*DM)     // 32768
#define NB 128                 // persistent blocks (<=148 SMs, 1 CTA/SM)

typedef unsigned long long u64;

// ================= baseline-PTX helpers (family-safe) =====
__device__ __forceinline__ uint32_t smem_u32(const void* p) {
    uint32_t a;
    asm("{ .reg .u64 t; cvta.to.shared.u64 t, %1; cvt.u32.u64 %0, t; }" : "=r"(a) : "l"(p));
    return a;
}
__device__ __forceinline__ void cpasync16(uint32_t s, const void* g) {
    asm volatile("cp.async.ca.shared.global [%0], [%1], 16;" :: "r"(s), "l"(g));
}
#define CP_COMMIT()  asm volatile("cp.async.commit_group;" ::: "memory")
#define CP_WAIT(n)   asm volatile("cp.async.wait_group %0;" :: "n"(n) : "memory")

__device__ __forceinline__ void ldsm4(uint32_t& r0, uint32_t& r1, uint32_t& r2, uint32_t& r3,
                                      uint32_t addr) {
    asm volatile("ldmatrix.sync.aligned.m8n8.x4.shared.b16 {%0,%1,%2,%3}, [%4];"
        : "=r"(r0), "=r"(r1), "=r"(r2), "=r"(r3) : "r"(addr));
}
__device__ __forceinline__ void mma16816(float* c, const uint32_t* a, const uint32_t* b) {
    asm volatile("mma.sync.aligned.m16n8k16.row.col.f32.bf16.bf16.f32 "
        "{%0,%1,%2,%3}, {%4,%5,%6,%7}, {%8,%9}, {%0,%1,%2,%3};"
        : "+f"(c[0]), "+f"(c[1]), "+f"(c[2]), "+f"(c[3])
        : "r"(a[0]), "r"(a[1]), "r"(a[2]), "r"(a[3]), "r"(b[0]), "r"(b[1]));
}
// packed fp32x2 (exact per-lane fp32)
__device__ __forceinline__ u64 pk2(float x) {
    u64 r; asm("mov.b64 %0, {%1, %1};" : "=l"(r) : "f"(x)); return r;
}
__device__ __forceinline__ void fma2(u64& d, u64 a, u64 b) {
    asm("fma.rn.f32x2 %0, %1, %2, %3;" : "=l"(d) : "l"(a), "l"(b), "l"(d));
}
__device__ __forceinline__ float2 upk(u64 v) {
    float2 f; asm("mov.b64 {%0, %1}, %2;" : "=f"(f.x), "=f"(f.y) : "l"(v)); return f;
}
// barrier primitives
__device__ __forceinline__ int ld_acq(const int* p) {
    int v; asm volatile("ld.acquire.gpu.b32 %0, [%1];" : "=r"(v) : "l"(p)); return v;
}
__device__ __forceinline__ void st_rel(int* p, int v) {
    asm volatile("st.release.gpu.b32 [%0], %1;" :: "l"(p), "r"(v));
}
__device__ __forceinline__ void red_addf(float* p, float v) {
    asm volatile("red.global.add.f32 [%0], %1;" :: "l"(p), "f"(v));
}

// ================= device scratch =================
__device__ float g_cent[KC*DM];
__device__ float g_sums[KC*DM];
__device__ int   g_counts[KC];
__device__ float g_centsq[KC];
__device__ float g_xsq[NROWS];
__device__ int   g_done;
__device__ float g_shift;
__device__ int   g_ucnt;
__device__ int   g_arr[NB];    // barrier arrival flags
__device__ int   g_rel;        // barrier release word
// bf16 split matrices
__device__ __nv_bfloat16 g_Ah[NROWS*SEQ];
__device__ __nv_bfloat16 g_Al[NROWS*SEQ];
__device__ __nv_bfloat16 g_Wh[DM*SEQ];
__device__ __nv_bfloat16 g_Wl[DM*SEQ];

// ================= init =================
__global__ void init_k(const float* __restrict__ centroids) {
    int i = blockIdx.x * blockDim.x + threadIdx.x;
    if (i == 0) { g_done = 0; g_shift = 0.f; g_ucnt = 0; g_rel = 0; }
    if (i < NB) g_arr[i] = 0;
    if (i < KC) g_counts[i] = 0;
    if (i < KC*DM) { g_cent[i] = centroids[i]; g_sums[i] = 0.f; }
}

// ================= bf16 split kernels =================
union BPack { __nv_bfloat16 h[8]; uint4 u; };

__global__ __launch_bounds__(256) void splitw_k(const float* __restrict__ W) {
    int i = (blockIdx.x * 256 + threadIdx.x) * 8;
    BPack ph, pl;
    #pragma unroll
    for (int j = 0; j < 8; j++) {
        float f = W[i + j];
        __nv_bfloat16 h = __float2bfloat16(f);
        ph.h[j] = h;
        pl.h[j] = __float2bfloat16(f - __bfloat162float(h));
    }
    *(uint4*)&g_Wh[i] = ph.u;
    *(uint4*)&g_Wl[i] = pl.u;
}

__global__ __launch_bounds__(256) void splitx_k(const float* __restrict__ x) {
    __shared__ float xs[64][65];
    int b  = blockIdx.x;
    int s0 = blockIdx.y * 64;
    int t  = threadIdx.x;
    const float* xp = x + ((size_t)b * SEQ + s0) * NV;
    int v = t & 63, i0 = t >> 6;
    #pragma unroll
    for (int j = 0; j < 16; j++)
        xs[i0 + j*4][v] = xp[(size_t)(i0 + j*4) * NV + v];
    __syncthreads();
    #pragma unroll
    for (int kx = 0; kx < 2; kx++) {
        int w = t + kx * 256;
        int v2 = w >> 3, seg = w & 7;
        BPack ph, pl;
        #pragma unroll
        for (int j = 0; j < 8; j++) {
            float f = xs[seg*8 + j][v2];
            __nv_bfloat16 h = __float2bfloat16(f);
            ph.h[j] = h;
            pl.h[j] = __float2bfloat16(f - __bfloat162float(h));
        }
        size_t off = (size_t)(b*64 + v2) * SEQ + s0 + seg*8;
        *(uint4*)&g_Ah[off] = ph.u;
        *(uint4*)&g_Al[off] = pl.u;
    }
}

// ================= HMMA GEMM (unchanged: 156us, tensor 55%) ====
#define ASTRIDE 80
#define TILE_B  (128*ASTRIDE)
#define BUF_B   (4*TILE_B)
#define SM_GEMM (2*BUF_B)

__global__ __launch_bounds__(256, 2) void mma_gemm_k(
    const float* __restrict__ bias, float* __restrict__ xe)
{
    extern __shared__ char smem[];
    const uint32_t sb = smem_u32(smem);
    const int t = threadIdx.x;
    const int wid = t >> 5, lane = t & 31;
    const int n0 = blockIdx.y * 128, d0 = blockIdx.x * 128;
    const int wm = wid >> 2, wn = wid & 3;

    const __nv_bfloat16* gm[4] = {
        g_Ah + (size_t)n0 * SEQ, g_Al + (size_t)n0 * SEQ,
        g_Wh + (size_t)d0 * SEQ, g_Wl + (size_t)d0 * SEQ };

    float acc[4][4][4] = {};

    const uint32_t aoff = (uint32_t)(wm*64 + (lane & 15)) * ASTRIDE + (lane >> 4) * 16;
    const uint32_t boff = (uint32_t)(wn*32 + ((lane >> 4) << 3) + (lane & 7)) * ASTRIDE
                        + (((lane >> 3) & 1) * 16);

    auto stage = [&](int ch, int buf) {
        const int s0 = ch * 32;
        const uint32_t bb = sb + buf * BUF_B;
        #pragma unroll
        for (int m = 0; m < 4; m++) {
            const __nv_bfloat16* g = gm[m];
            const uint32_t sm = bb + m * TILE_B;
            int r0 = t >> 2,        c0 = t & 3;
            int r1 = (t+256) >> 2,  c1 = (t+256) & 3;
            cpasync16(sm + r0*ASTRIDE + c0*16, g + (size_t)r0 * SEQ + s0 + c0*8);
            cpasync16(sm + r1*ASTRIDE + c1*16, g + (size_t)r1 * SEQ + s0 + c1*8);
        }
        CP_COMMIT();
    };

    stage(0, 0);
    for (int ch = 0; ch < SEQ/32; ch++) {
        const int buf = ch & 1;
        const bool more = (ch + 1) < SEQ/32;
        if (more) { stage(ch + 1, buf ^ 1); CP_WAIT(1); }
        else      { CP_WAIT(0); }
        __syncthreads();

        const uint32_t bb = sb + buf * BUF_B;
        #pragma unroll
        for (int ks = 0; ks < 2; ks++) {
            const uint32_t ko = ks * 32;
            uint32_t Ah[4][4], Al[4][4], Bh[2][4], Bl[2][4];
            #pragma unroll
            for (int mf = 0; mf < 4; mf++)
                ldsm4(Ah[mf][0], Ah[mf][1], Ah[mf][2], Ah[mf][3],
                      bb + 0*TILE_B + aoff + mf*16*ASTRIDE + ko);
            #pragma unroll
            for (int p = 0; p < 2; p++)
                ldsm4(Bh[p][0], Bh[p][1], Bh[p][2], Bh[p][3],
                      bb + 2*TILE_B + boff + p*16*ASTRIDE + ko);
            #pragma unroll
            for (int mf = 0; mf < 4; mf++)
                #pragma unroll
                for (int nf = 0; nf < 4; nf++)
                    mma16816(acc[mf][nf], Ah[mf], &Bh[nf>>1][(nf&1)*2]);
            #pragma unroll
            for (int mf = 0; mf < 4; mf++)
                ldsm4(Al[mf][0], Al[mf][1], Al[mf][2], Al[mf][3],
                      bb + 1*TILE_B + aoff + mf*16*ASTRIDE + ko);
            #pragma unroll
            for (int mf = 0; mf < 4; mf++)
                #pragma unroll
                for (int nf = 0; nf < 4; nf++)
                    mma16816(acc[mf][nf], Al[mf], &Bh[nf>>1][(nf&1)*2]);
            #pragma unroll
            for (int p = 0; p < 2; p++)
                ldsm4(Bl[p][0], Bl[p][1], Bl[p][2], Bl[p][3],
                      bb + 3*TILE_B + boff + p*16*ASTRIDE + ko);
            #pragma unroll
            for (int mf = 0; mf < 4; mf++)
                #pragma unroll
                for (int nf = 0; nf < 4; nf++)
                    mma16816(acc[mf][nf], Ah[mf], &Bl[nf>>1][(nf&1)*2]);
        }
        __syncthreads();
    }

    const int tg = lane >> 2, tq = lane & 3;
    #pragma unroll
    for (int mf = 0; mf < 4; mf++) {
        const int r0 = n0 + wm*64 + mf*16 + tg;
        #pragma unroll
        for (int nf = 0; nf < 4; nf++) {
            const int c0 = d0 + wn*32 + nf*8 + tq*2;
            const float2 bv = *(const float2*)(bias + c0);
            float2 o0 = make_float2(acc[mf][nf][0] + bv.x, acc[mf][nf][1] + bv.y);
            float2 o1 = make_float2(acc[mf][nf][2] + bv.x, acc[mf][nf][3] + bv.y);
            *(float2*)(xe + (size_t)r0      * DM + c0) = o0;
            *(float2*)(xe + (size_t)(r0+8)  * DM + c0) = o1;
        }
    }
}

// ================= persistent k-means =================
// dyn smem: xeT (512 x 68 floats, transposed block rows) + 32KB pool
#define XET_FLOATS (512*68)            // 34816 floats = 139264 B
#define SM_KM (XET_FLOATS*4 + 32768)   // 172032 B

// fast grid barrier: per-block arrival flags + block-0 poller + release word
__device__ __forceinline__ void gridbar(int gen) {
    __threadfence();
    __syncthreads();
    if (blockIdx.x == 0) {
        if (threadIdx.x < NB) {
            if (threadIdx.x == 0) st_rel(&g_arr[0], gen);
            while (ld_acq(&g_arr[threadIdx.x]) < gen) { }
        }
        __syncthreads();
        if (threadIdx.x == 0) st_rel(&g_rel, gen);
    } else {
        if (threadIdx.x == 0) {
            st_rel(&g_arr[blockIdx.x], gen);
            while (ld_acq(&g_rel) < gen) { }
        }
        __syncthreads();
    }
}

__global__ __launch_bounds__(256, 1) void kmeans_k(
    const float* __restrict__ xe, float* __restrict__ out)
{
    extern __shared__ float dsm[];
    float* xeT  = dsm;                  // [s 0..511][row 0..63] stride 68
    float* pool = dsm + XET_FLOATS;     // 8192 floats scratch
    __shared__ int sids[64];
    __shared__ int cnts[KC];

    const int t   = threadIdx.x;
    const int blk = blockIdx.x;
    const int n0  = blk * 64;
    int bgen = 0;

    // ---- pre-phase: xsq, centsq, transpose-stage xeT ----
    {
        int row4 = t >> 2, part = t & 3;
        const float* xr = xe + (size_t)(n0 + row4) * DM + part * 128;
        float s = 0.f;
        #pragma unroll
        for (int q = 0; q < 32; q++) {
            float4 v = *(const float4*)(xr + q*4);
            s += v.x*v.x + v.y*v.y + v.z*v.z + v.w*v.w;
        }
        s += __shfl_xor_sync(~0u, s, 1);
        s += __shfl_xor_sync(~0u, s, 2);
        if (part == 0) g_xsq[n0 + row4] = s;

        if (blk < KC) {
            float c1 = __ldcg(&g_cent[blk*DM + t]);
            float c2 = __ldcg(&g_cent[blk*DM + 256 + t]);
            pool[t] = c1*c1 + c2*c2;
            __syncthreads();
            for (int o = 128; o; o >>= 1) { if (t < o) pool[t] += pool[t+o]; __syncthreads(); }
            if (t == 0) g_centsq[blk] = pool[0];
        }

        // stage xeT once (conflict-free lane map: consecutive lanes = rows)
        const int row = t & 63, s4b = t >> 6;
        #pragma unroll
        for (int j = 0; j < 32; j++) {
            int s4 = s4b + j*4;
            float4 v = *(const float4*)(xe + (size_t)(n0+row)*DM + s4*4);
            xeT[(s4*4+0)*68+row] = v.x;
            xeT[(s4*4+1)*68+row] = v.y;
            xeT[(s4*4+2)*68+row] = v.z;
            xeT[(s4*4+3)*68+row] = v.w;
        }
        __syncthreads();
    }
    gridbar(++bgen);

    const int tn = t & 15, td = t >> 4;

    for (int it = 0; it < MAX_ITER; it++) {
        if (__ldcg(&g_done)) break;

        // ---------- PHASE A: assign (xeT persistent; stage only cent) ----------
        {
            float* cs = pool;                        // [32 s][68] per chunk
            u64 acc2[4][2] = {};
            const int crow = t & 63, cq = t >> 6;    // conflict-free map
            for (int c0 = 0; c0 < DM; c0 += 32) {
                #pragma unroll
                for (int j = 0; j < 2; j++) {
                    int q = cq + j*4;
                    float4 w = __ldcg((const float4*)(g_cent + crow*DM + c0 + q*4));
                    cs[(q*4+0)*68+crow] = w.x; cs[(q*4+1)*68+crow] = w.y;
                    cs[(q*4+2)*68+crow] = w.z; cs[(q*4+3)*68+crow] = w.w;
                }
                __syncthreads();
                #pragma unroll
                for (int s = 0; s < 32; s++) {
                    float4 a = *(const float4*)&xeT[(c0+s)*68 + tn*4];
                    ulonglong2 b = *(const ulonglong2*)&cs[s*68 + td*4];
                    float av[4] = {a.x, a.y, a.z, a.w};
                    #pragma unroll
                    for (int i = 0; i < 4; i++) {
                        u64 ap = pk2(av[i]);
                        fma2(acc2[i][0], ap, b.x);
                        fma2(acc2[i][1], ap, b.y);
                    }
                }
                __syncthreads();
            }
            float xq[4], cq2[4];
            #pragma unroll
            for (int i = 0; i < 4; i++) xq[i] = g_xsq[n0 + tn*4 + i];
            #pragma unroll
            for (int j = 0; j < 4; j++) cq2[j] = __ldcg(&g_centsq[td*4 + j]);
            float* ds = pool;                        // [64 row][68]
            #pragma unroll
            for (int i = 0; i < 4; i++) {
                float2 p0 = upk(acc2[i][0]), p1 = upk(acc2[i][1]);
                float b = xq[i];
                ds[(tn*4+i)*68 + td*4+0] = b - 2.f*p0.x + cq2[0];
                ds[(tn*4+i)*68 + td*4+1] = b - 2.f*p0.y + cq2[1];
                ds[(tn*4+i)*68 + td*4+2] = b - 2.f*p1.x + cq2[2];
                ds[(tn*4+i)*68 + td*4+3] = b - 2.f*p1.y + cq2[3];
            }
            __syncthreads();
            if (t < 64) {
                float best = 3.4e38f; int bid = 0;
                #pragma unroll 8
                for (int k = 0; k < KC; k++) {
                    float v = ds[t*68 + k];
                    if (v < best) { best = v; bid = k; }
                }
                sids[t] = bid;
            }
            __syncthreads();
        }
        gridbar(++bgen);

        // ---------- PHASE B: accumulate via direct global RED ----------
        {
            if (t < KC) cnts[t] = 0;
            __syncthreads();
            if (t < 64) atomicAdd(&cnts[sids[t]], 1);
            const int d2 = t * 2;
            #pragma unroll 4
            for (int r = 0; r < 64; r++) {
                int id = sids[r];
                float2 v = *(const float2*)(xe + (size_t)(n0+r)*DM + d2);
                float* dst = g_sums + id*DM + d2;
                red_addf(dst,     v.x);
                red_addf(dst + 1, v.y);
            }
            __syncthreads();
            if (t < KC && cnts[t]) atomicAdd(&g_counts[t], cnts[t]);
        }
        gridbar(++bgen);

        // ---------- PHASE C: centroid update + done check ----------
        if (blk < KC) {
            const int k = blk;
            float cnt = (float)__ldcg(&g_counts[k]);
            float inv = 1.f / fmaxf(cnt, 1.f);
            bool  has = cnt > 0.f;
            float sh = 0.f, cq = 0.f;
            #pragma unroll
            for (int j = 0; j < 2; j++) {
                int e = k*DM + t + j*256;
                float old = g_cent[e];
                float nc  = has ? __ldcg(&g_sums[e]) * inv : old;
                g_cent[e] = nc;
                g_sums[e] = 0.f;
                float dd = nc - old;
                sh += dd*dd;
                cq += nc*nc;
            }
            pool[t] = sh; pool[256 + t] = cq;
            __syncthreads();
            for (int o = 128; o; o >>= 1) {
                if (t < o) { pool[t] += pool[t+o]; pool[256+t] += pool[256+t+o]; }
                __syncthreads();
            }
            if (t == 0) {
                g_centsq[k] = pool[256];
                atomicAdd(&g_shift, pool[0]);
                g_counts[k] = 0;
                __threadfence();
                if (atomicAdd(&g_ucnt, 1) == KC - 1) {
                    float tot = atomicAdd(&g_shift, 0.f);
                    if (sqrtf(tot) < TOL) g_done = 1;
                    g_shift = 0.f;
                    atomicExch(&g_ucnt, 0);
                }
            }
        }
        gridbar(++bgen);
    }

    // ---------- finalize: prob one-hot + cent copy ----------
    for (int i = t; i < 1024; i += 256) {
        int row = i >> 4, kq = (i & 15) << 2;
        int id = sids[row];
        float4 o = make_float4(kq+0 == id ? 1.f : 0.f, kq+1 == id ? 1.f : 0.f,
                               kq+2 == id ? 1.f : 0.f, kq+3 == id ? 1.f : 0.f);
        *(float4*)(out + (size_t)(n0+row)*KC + kq) = o;
    }
    if (blk < KC) {
        #pragma unroll
        for (int i = t; i < 128; i += 256) {
            float4 c = *(const float4*)(g_cent + blk*DM + i*4);   // own writes
            *(float4*)(out + PROB_ELEMS + blk*DM + i*4) = c;
        }
    }
}

// ================= launch =================
extern "C" void kernel_launch(void* const* d_in, const int* in_sizes, int n_in,
                              void* d_out, int out_size) {
    const float* x         = (const float*)d_in[0];
    const float* W         = (const float*)d_in[1];
    const float* bias      = (const float*)d_in[2];
    const float* centroids = (const float*)d_in[3];
    float* out = (float*)d_out;
    float* xe  = out + PROB_ELEMS + CENT_ELEMS;   // x_emb straight to output

    cudaFuncSetAttribute(mma_gemm_k, cudaFuncAttributeMaxDynamicSharedMemorySize, SM_GEMM);
    cudaFuncSetAttribute(kmeans_k,   cudaFuncAttributeMaxDynamicSharedMemorySize, SM_KM);

    init_k<<<(KC*DM + 255)/256, 256>>>(centroids);
    splitw_k<<<(DM*SEQ)/(256*8), 256>>>(W);
    splitx_k<<<dim3(BS, SEQ/64), 256>>>(x);
    mma_gemm_k<<<dim3(DM/128, NROWS/128), 256, SM_GEMM>>>(bias, xe);
    kmeans_k<<<NB, 256, SM_KM>>>(xe, out);
}

// round 14
// speedup vs baseline: 2.5182x; 1.1174x over previous
#include <cuda_runtime.h>
#include <cuda_bf16.h>
#include <cstdint>

#define BS 128
#define SEQ 2048
#define NV 64
#define DM 512
#define KC 64
#define NROWS (BS*NV)          // 8192
#define MAX_ITER 10
#define TOL 1e-4f
#define PROB_ELEMS (BS*NV*KC)  // 524288
#define CENT_ELEMS (KC*DM)     // 32768
#define NB 128                 // persistent blocks (<=148 SMs, 1 CTA/SM)

typedef unsigned long long u64;

// ================= baseline-PTX helpers (family-safe) =====
__device__ __forceinline__ uint32_t smem_u32(const void* p) {
    uint32_t a;
    asm("{ .reg .u64 t; cvta.to.shared.u64 t, %1; cvt.u32.u64 %0, t; }" : "=r"(a) : "l"(p));
    return a;
}
__device__ __forceinline__ void cpasync16(uint32_t s, const void* g) {
    asm volatile("cp.async.ca.shared.global [%0], [%1], 16;" :: "r"(s), "l"(g));
}
#define CP_COMMIT()  asm volatile("cp.async.commit_group;" ::: "memory")
#define CP_WAIT(n)   asm volatile("cp.async.wait_group %0;" :: "n"(n) : "memory")

__device__ __forceinline__ void ldsm4(uint32_t& r0, uint32_t& r1, uint32_t& r2, uint32_t& r3,
                                      uint32_t addr) {
    asm volatile("ldmatrix.sync.aligned.m8n8.x4.shared.b16 {%0,%1,%2,%3}, [%4];"
        : "=r"(r0), "=r"(r1), "=r"(r2), "=r"(r3) : "r"(addr));
}
__device__ __forceinline__ void mma16816(float* c, const uint32_t* a, const uint32_t* b) {
    asm volatile("mma.sync.aligned.m16n8k16.row.col.f32.bf16.bf16.f32 "
        "{%0,%1,%2,%3}, {%4,%5,%6,%7}, {%8,%9}, {%0,%1,%2,%3};"
        : "+f"(c[0]), "+f"(c[1]), "+f"(c[2]), "+f"(c[3])
        : "r"(a[0]), "r"(a[1]), "r"(a[2]), "r"(a[3]), "r"(b[0]), "r"(b[1]));
}
// packed fp32x2 (exact per-lane fp32)
__device__ __forceinline__ u64 pk2(float x) {
    u64 r; asm("mov.b64 %0, {%1, %1};" : "=l"(r) : "f"(x)); return r;
}
__device__ __forceinline__ void fma2(u64& d, u64 a, u64 b) {
    asm("fma.rn.f32x2 %0, %1, %2, %3;" : "=l"(d) : "l"(a), "l"(b), "l"(d));
}
__device__ __forceinline__ float2 upk(u64 v) {
    float2 f; asm("mov.b64 {%0, %1}, %2;" : "=f"(f.x), "=f"(f.y) : "l"(v)); return f;
}
// barrier primitives
__device__ __forceinline__ int ld_acq(const int* p) {
    int v; asm volatile("ld.acquire.gpu.b32 %0, [%1];" : "=r"(v) : "l"(p)); return v;
}
__device__ __forceinline__ void st_rel(int* p, int v) {
    asm volatile("st.release.gpu.b32 [%0], %1;" :: "l"(p), "r"(v));
}
__device__ __forceinline__ void red_addf(float* p, float v) {
    asm volatile("red.global.add.f32 [%0], %1;" :: "l"(p), "f"(v));
}

// ================= device scratch =================
__device__ float g_cent[KC*DM];
__device__ float g_sums[KC*DM];
__device__ int   g_counts[KC];
__device__ float g_centsq[KC];
__device__ int   g_done;
__device__ float g_shift;
__device__ int   g_c1;   // all-blocks barrier counter (monotonic)
__device__ int   g_r1;   // all-blocks release word
__device__ int   g_c2;   // owner (KC) barrier counter
__device__ int   g_r2;   // owner barrier release
// bf16 split matrices
__device__ __nv_bfloat16 g_Ah[NROWS*SEQ];
__device__ __nv_bfloat16 g_Al[NROWS*SEQ];
__device__ __nv_bfloat16 g_Wh[DM*SEQ];
__device__ __nv_bfloat16 g_Wl[DM*SEQ];

// ================= init =================
__global__ void init_k(const float* __restrict__ centroids) {
    int i = blockIdx.x * blockDim.x + threadIdx.x;
    if (i == 0) {
        g_done = 0; g_shift = 0.f;
        g_c1 = 0; g_r1 = 0; g_c2 = 0; g_r2 = 0;
    }
    if (i < KC) g_counts[i] = 0;
    if (i < KC*DM) { g_cent[i] = centroids[i]; g_sums[i] = 0.f; }
}

// ================= bf16 split kernels =================
union BPack { __nv_bfloat16 h[8]; uint4 u; };

__global__ __launch_bounds__(256) void splitw_k(const float* __restrict__ W) {
    int i = (blockIdx.x * 256 + threadIdx.x) * 8;
    BPack ph, pl;
    #pragma unroll
    for (int j = 0; j < 8; j++) {
        float f = W[i + j];
        __nv_bfloat16 h = __float2bfloat16(f);
        ph.h[j] = h;
        pl.h[j] = __float2bfloat16(f - __bfloat162float(h));
    }
    *(uint4*)&g_Wh[i] = ph.u;
    *(uint4*)&g_Wl[i] = pl.u;
}

__global__ __launch_bounds__(256) void splitx_k(const float* __restrict__ x) {
    __shared__ float xs[64][65];
    int b  = blockIdx.x;
    int s0 = blockIdx.y * 64;
    int t  = threadIdx.x;
    const float* xp = x + ((size_t)b * SEQ + s0) * NV;
    int v = t & 63, i0 = t >> 6;
    #pragma unroll
    for (int j = 0; j < 16; j++)
        xs[i0 + j*4][v] = xp[(size_t)(i0 + j*4) * NV + v];
    __syncthreads();
    #pragma unroll
    for (int kx = 0; kx < 2; kx++) {
        int w = t + kx * 256;
        int v2 = w >> 3, seg = w & 7;
        BPack ph, pl;
        #pragma unroll
        for (int j = 0; j < 8; j++) {
            float f = xs[seg*8 + j][v2];
            __nv_bfloat16 h = __float2bfloat16(f);
            ph.h[j] = h;
            pl.h[j] = __float2bfloat16(f - __bfloat162float(h));
        }
        size_t off = (size_t)(b*64 + v2) * SEQ + s0 + seg*8;
        *(uint4*)&g_Ah[off] = ph.u;
        *(uint4*)&g_Al[off] = pl.u;
    }
}

// ================= HMMA GEMM (unchanged: ~154us, tensor 55%) ====
#define ASTRIDE 80
#define TILE_B  (128*ASTRIDE)
#define BUF_B   (4*TILE_B)
#define SM_GEMM (2*BUF_B)

__global__ __launch_bounds__(256, 2) void mma_gemm_k(
    const float* __restrict__ bias, float* __restrict__ xe)
{
    extern __shared__ char smem[];
    const uint32_t sb = smem_u32(smem);
    const int t = threadIdx.x;
    const int wid = t >> 5, lane = t & 31;
    const int n0 = blockIdx.y * 128, d0 = blockIdx.x * 128;
    const int wm = wid >> 2, wn = wid & 3;

    const __nv_bfloat16* gm[4] = {
        g_Ah + (size_t)n0 * SEQ, g_Al + (size_t)n0 * SEQ,
        g_Wh + (size_t)d0 * SEQ, g_Wl + (size_t)d0 * SEQ };

    float acc[4][4][4] = {};

    const uint32_t aoff = (uint32_t)(wm*64 + (lane & 15)) * ASTRIDE + (lane >> 4) * 16;
    const uint32_t boff = (uint32_t)(wn*32 + ((lane >> 4) << 3) + (lane & 7)) * ASTRIDE
                        + (((lane >> 3) & 1) * 16);

    auto stage = [&](int ch, int buf) {
        const int s0 = ch * 32;
        const uint32_t bb = sb + buf * BUF_B;
        #pragma unroll
        for (int m = 0; m < 4; m++) {
            const __nv_bfloat16* g = gm[m];
            const uint32_t sm = bb + m * TILE_B;
            int r0 = t >> 2,        c0 = t & 3;
            int r1 = (t+256) >> 2,  c1 = (t+256) & 3;
            cpasync16(sm + r0*ASTRIDE + c0*16, g + (size_t)r0 * SEQ + s0 + c0*8);
            cpasync16(sm + r1*ASTRIDE + c1*16, g + (size_t)r1 * SEQ + s0 + c1*8);
        }
        CP_COMMIT();
    };

    stage(0, 0);
    for (int ch = 0; ch < SEQ/32; ch++) {
        const int buf = ch & 1;
        const bool more = (ch + 1) < SEQ/32;
        if (more) { stage(ch + 1, buf ^ 1); CP_WAIT(1); }
        else      { CP_WAIT(0); }
        __syncthreads();

        const uint32_t bb = sb + buf * BUF_B;
        #pragma unroll
        for (int ks = 0; ks < 2; ks++) {
            const uint32_t ko = ks * 32;
            uint32_t Ah[4][4], Al[4][4], Bh[2][4], Bl[2][4];
            #pragma unroll
            for (int mf = 0; mf < 4; mf++)
                ldsm4(Ah[mf][0], Ah[mf][1], Ah[mf][2], Ah[mf][3],
                      bb + 0*TILE_B + aoff + mf*16*ASTRIDE + ko);
            #pragma unroll
            for (int p = 0; p < 2; p++)
                ldsm4(Bh[p][0], Bh[p][1], Bh[p][2], Bh[p][3],
                      bb + 2*TILE_B + boff + p*16*ASTRIDE + ko);
            #pragma unroll
            for (int mf = 0; mf < 4; mf++)
                #pragma unroll
                for (int nf = 0; nf < 4; nf++)
                    mma16816(acc[mf][nf], Ah[mf], &Bh[nf>>1][(nf&1)*2]);
            #pragma unroll
            for (int mf = 0; mf < 4; mf++)
                ldsm4(Al[mf][0], Al[mf][1], Al[mf][2], Al[mf][3],
                      bb + 1*TILE_B + aoff + mf*16*ASTRIDE + ko);
            #pragma unroll
            for (int mf = 0; mf < 4; mf++)
                #pragma unroll
                for (int nf = 0; nf < 4; nf++)
                    mma16816(acc[mf][nf], Al[mf], &Bh[nf>>1][(nf&1)*2]);
            #pragma unroll
            for (int p = 0; p < 2; p++)
                ldsm4(Bl[p][0], Bl[p][1], Bl[p][2], Bl[p][3],
                      bb + 3*TILE_B + boff + p*16*ASTRIDE + ko);
            #pragma unroll
            for (int mf = 0; mf < 4; mf++)
                #pragma unroll
                for (int nf = 0; nf < 4; nf++)
                    mma16816(acc[mf][nf], Ah[mf], &Bl[nf>>1][(nf&1)*2]);
        }
        __syncthreads();
    }

    const int tg = lane >> 2, tq = lane & 3;
    #pragma unroll
    for (int mf = 0; mf < 4; mf++) {
        const int r0 = n0 + wm*64 + mf*16 + tg;
        #pragma unroll
        for (int nf = 0; nf < 4; nf++) {
            const int c0 = d0 + wn*32 + nf*8 + tq*2;
            const float2 bv = *(const float2*)(bias + c0);
            float2 o0 = make_float2(acc[mf][nf][0] + bv.x, acc[mf][nf][1] + bv.y);
            float2 o1 = make_float2(acc[mf][nf][2] + bv.x, acc[mf][nf][3] + bv.y);
            *(float2*)(xe + (size_t)r0      * DM + c0) = o0;
            *(float2*)(xe + (size_t)(r0+8)  * DM + c0) = o1;
        }
    }
}

// ================= persistent k-means =================
// xeT: transposed block rows [s][row] stride 68, +4-float skew per 128-s block.
#define XIDX(s) ((s)*68 + (((s) >> 7) << 2))
#define XET_FLOATS 34832                 // > XIDX(511)+56+8
#define CSL 2180                         // cent slice stride: 32*68 + 4 skew
#define POOL_FLOATS (4*CSL)              // 8720 (>= ds 64*68)
#define SM_KM ((XET_FLOATS + POOL_FLOATS)*4)   // 174208 B

__device__ __forceinline__ void barrier_all(int inst) {
    __threadfence();
    __syncthreads();
    if (threadIdx.x == 0) {
        int old = atomicAdd(&g_c1, 1);
        if (old == inst * NB - 1) st_rel(&g_r1, inst);
        while (ld_acq(&g_r1) < inst) { }
    }
    __syncthreads();
}

__global__ __launch_bounds__(256, 1) void kmeans_k(
    const float* __restrict__ xe, float* __restrict__ out)
{
    extern __shared__ float dsm[];
    float* xeT  = dsm;                   // skewed transposed xe rows
    float* pool = dsm + XET_FLOATS;      // cent slices / ds / reductions
    __shared__ int   sids[64];
    __shared__ int   cnts[KC];
    __shared__ float sxq[64];

    const int t    = threadIdx.x;
    const int blk  = blockIdx.x;
    const int n0   = blk * 64;
    const int lane = t & 31, w = t >> 5;
    int ab = 0;

    // ---- pre-phase: xsq (smem), centsq, stage xeT ----
    {
        int row4 = t >> 2, part = t & 3;
        const float* xr = xe + (size_t)(n0 + row4) * DM + part * 128;
        float s = 0.f;
        #pragma unroll
        for (int q = 0; q < 32; q++) {
            float4 v = *(const float4*)(xr + q*4);
            s += v.x*v.x + v.y*v.y + v.z*v.z + v.w*v.w;
        }
        s += __shfl_xor_sync(~0u, s, 1);
        s += __shfl_xor_sync(~0u, s, 2);
        if (part == 0) sxq[row4] = s;

        if (blk < KC) {
            float c1 = __ldcg(&g_cent[blk*DM + t]);
            float c2 = __ldcg(&g_cent[blk*DM + 256 + t]);
            pool[t] = c1*c1 + c2*c2;
            __syncthreads();
            for (int o = 128; o; o >>= 1) { if (t < o) pool[t] += pool[t+o]; __syncthreads(); }
            if (t == 0) g_centsq[blk] = pool[0];
        }

        // stage xeT once
        const int row = t & 63, s4b = t >> 6;
        #pragma unroll
        for (int j = 0; j < 32; j++) {
            int s4 = s4b + j*4;
            float4 v = *(const float4*)(xe + (size_t)(n0+row)*DM + s4*4);
            xeT[XIDX(s4*4+0)+row] = v.x;
            xeT[XIDX(s4*4+1)+row] = v.y;
            xeT[XIDX(s4*4+2)+row] = v.z;
            xeT[XIDX(s4*4+3)+row] = v.w;
        }
        __syncthreads();
    }
    barrier_all(++ab);

    // phase-A thread mapping: split-K=4, 8x8 tiles
    const int ks = lane & 3;                        // K-quarter
    const int pidx = lane >> 2;                     // 0..7
    const int perm8[8] = {0, 2, 4, 6, 1, 3, 5, 7};
    const int tc = perm8[pidx];                     // col group
    const int r0 = w * 8;                           // rows w*8..+7
    const int c0 = tc * 8;                          // cols

    for (int it = 0; it < MAX_ITER; it++) {
        if (__ldcg(&g_done)) break;

        // ---------- PHASE A: assign (split-K f32x2 GEMM) ----------
        {
            u64 acc[8][4] = {};
            const int crow = t & 63, q = t >> 6;    // staging map
            for (int c = 0; c < 4; c++) {
                // stage 4 K-slices of 32 dims each, skewed
                #pragma unroll
                for (int ksl = 0; ksl < 4; ksl++) {
                    float* base = pool + ksl * CSL;
                    #pragma unroll
                    for (int j = 0; j < 2; j++) {
                        int q4 = q + j*4;           // 0..7
                        float4 wv = __ldcg((const float4*)(g_cent
                                      + crow*DM + ksl*128 + c*32 + q4*4));
                        base[(q4*4+0)*68 + crow] = wv.x;
                        base[(q4*4+1)*68 + crow] = wv.y;
                        base[(q4*4+2)*68 + crow] = wv.z;
                        base[(q4*4+3)*68 + crow] = wv.w;
                    }
                }
                __syncthreads();
                const float* cb0 = pool + ks * CSL;
                #pragma unroll 4
                for (int i = 0; i < 32; i++) {
                    int gs = ks*128 + c*32 + i;
                    const float* xr = &xeT[XIDX(gs) + r0];
                    float4 a0 = *(const float4*)xr;
                    float4 a1 = *(const float4*)(xr + 4);
                    const float* cb = cb0 + i*68 + c0;
                    ulonglong2 b0 = *(const ulonglong2*)cb;
                    ulonglong2 b1 = *(const ulonglong2*)(cb + 4);
                    float av[8] = {a0.x, a0.y, a0.z, a0.w, a1.x, a1.y, a1.z, a1.w};
                    u64 bv[4] = {b0.x, b0.y, b1.x, b1.y};
                    #pragma unroll
                    for (int r = 0; r < 8; r++) {
                        u64 ap = pk2(av[r]);
                        fma2(acc[r][0], ap, bv[0]);
                        fma2(acc[r][1], ap, bv[1]);
                        fma2(acc[r][2], ap, bv[2]);
                        fma2(acc[r][3], ap, bv[3]);
                    }
                }
                __syncthreads();
            }

            // cross-K shfl reduce + distance write (pool reused as ds[64][68])
            float cq[8];
            #pragma unroll
            for (int j = 0; j < 8; j++) cq[j] = __ldcg(&g_centsq[c0 + j]);
            float* ds = pool;
            #pragma unroll
            for (int r = 0; r < 8; r++) {
                float res[8];
                #pragma unroll
                for (int j = 0; j < 4; j++) {
                    u64 v = acc[r][j];
                    u64 o = __shfl_xor_sync(~0u, v, 1);
                    float2 f = upk(v), g2 = upk(o);
                    f.x += g2.x; f.y += g2.y;
                    f.x += __shfl_xor_sync(~0u, f.x, 2);
                    f.y += __shfl_xor_sync(~0u, f.y, 2);
                    res[2*j] = f.x; res[2*j+1] = f.y;
                }
                if ((r >> 1) == ks) {
                    int row = r0 + r;
                    float xq = sxq[row];
                    float4 o0 = make_float4(xq - 2.f*res[0] + cq[0], xq - 2.f*res[1] + cq[1],
                                            xq - 2.f*res[2] + cq[2], xq - 2.f*res[3] + cq[3]);
                    float4 o1 = make_float4(xq - 2.f*res[4] + cq[4], xq - 2.f*res[5] + cq[5],
                                            xq - 2.f*res[6] + cq[6], xq - 2.f*res[7] + cq[7]);
                    *(float4*)&ds[row*68 + c0]     = o0;
                    *(float4*)&ds[row*68 + c0 + 4] = o1;
                }
            }
            __syncthreads();
            if (t < 64) {
                float best = 3.4e38f; int bid = 0;
                #pragma unroll 8
                for (int k = 0; k < KC; k++) {
                    float v = ds[t*68 + k];
                    if (v < best) { best = v; bid = k; }
                }
                sids[t] = bid;
            }
            __syncthreads();
        }

        // ---------- PHASE B (fused, no barrier): RED own rows ----------
        {
            if (t < KC) cnts[t] = 0;
            __syncthreads();
            if (t < 64) atomicAdd(&cnts[sids[t]], 1);
            const int d2 = t * 2;
            #pragma unroll 4
            for (int r = 0; r < 64; r++) {
                int id = sids[r];
                float2 v = *(const float2*)(xe + (size_t)(n0+r)*DM + d2);
                float* dst = g_sums + id*DM + d2;
                red_addf(dst,     v.x);
                red_addf(dst + 1, v.y);
            }
            __syncthreads();
            if (t < KC && cnts[t]) atomicAdd(&g_counts[t], cnts[t]);
        }
        barrier_all(++ab);

        // ---------- PHASE C: owners update centroids; last owner decides ----------
        if (blk < KC) {
            const int k = blk;
            float cnt = (float)__ldcg(&g_counts[k]);
            float inv = 1.f / fmaxf(cnt, 1.f);
            bool  has = cnt > 0.f;
            float sh = 0.f, cq = 0.f;
            #pragma unroll
            for (int j = 0; j < 2; j++) {
                int e = k*DM + t + j*256;
                float old = g_cent[e];
                float nc  = has ? __ldcg(&g_sums[e]) * inv : old;
                g_cent[e] = nc;
                g_sums[e] = 0.f;
                float dd = nc - old;
                sh += dd*dd;
                cq += nc*nc;
            }
            pool[t] = sh; pool[256 + t] = cq;
            __syncthreads();
            for (int o = 128; o; o >>= 1) {
                if (t < o) { pool[t] += pool[t+o]; pool[256+t] += pool[256+t+o]; }
                __syncthreads();
            }
            if (t == 0) {
                g_centsq[k] = pool[256];
                atomicAdd(&g_shift, pool[0]);
                g_counts[k] = 0;
                __threadfence();
                int old = atomicAdd(&g_c2, 1);
                if (old == (it + 1) * KC - 1) {
                    float tot = atomicAdd(&g_shift, 0.f);
                    if (sqrtf(tot) < TOL) g_done = 1;
                    g_shift = 0.f;
                    __threadfence();
                    st_rel(&g_r2, it + 1);
                }
            }
        }
        if (t == 0) { while (ld_acq(&g_r2) < it + 1) { } }
        __syncthreads();
    }

    // ---------- finalize: prob one-hot + cent copy ----------
    for (int i = t; i < 1024; i += 256) {
        int row = i >> 4, kq = (i & 15) << 2;
        int id = sids[row];
        float4 o = make_float4(kq+0 == id ? 1.f : 0.f, kq+1 == id ? 1.f : 0.f,
                               kq+2 == id ? 1.f : 0.f, kq+3 == id ? 1.f : 0.f);
        *(float4*)(out + (size_t)(n0+row)*KC + kq) = o;
    }
    if (blk < KC) {
        #pragma unroll
        for (int i = t; i < 128; i += 256) {
            float4 c = *(const float4*)(g_cent + blk*DM + i*4);   // owner's own writes
            *(float4*)(out + PROB_ELEMS + blk*DM + i*4) = c;
        }
    }
}

// ================= launch =================
extern "C" void kernel_launch(void* const* d_in, const int* in_sizes, int n_in,
                              void* d_out, int out_size) {
    const float* x         = (const float*)d_in[0];
    const float* W         = (const float*)d_in[1];
    const float* bias      = (const float*)d_in[2];
    const float* centroids = (const float*)d_in[3];
    float* out = (float*)d_out;
    float* xe  = out + PROB_ELEMS + CENT_ELEMS;   // x_emb straight to output

    cudaFuncSetAttribute(mma_gemm_k, cudaFuncAttributeMaxDynamicSharedMemorySize, SM_GEMM);
    cudaFuncSetAttribute(kmeans_k,   cudaFuncAttributeMaxDynamicSharedMemorySize, SM_KM);

    init_k<<<(KC*DM + 255)/256, 256>>>(centroids);
    splitw_k<<<(DM*SEQ)/(256*8), 256>>>(W);
    splitx_k<<<dim3(BS, SEQ/64), 256>>>(x);
    mma_gemm_k<<<dim3(DM/128, NROWS/128), 256, SM_GEMM>>>(bias, xe);
    kmeans_k<<<NB, 256, SM_KM>>>(xe, out);
}

// round 15
// speedup vs baseline: 2.6976x; 1.0712x over previous
#include <cuda_runtime.h>
#include <cuda_bf16.h>
#include <cstdint>

#define BS 128
#define SEQ 2048
#define NV 64
#define DM 512
#define KC 64
#define NROWS (BS*NV)          // 8192
#define MAX_ITER 10
#define TOL 1e-4f
#define PROB_ELEMS (BS*NV*KC)  // 524288
#define CENT_ELEMS (KC*DM)     // 32768
#define NB 128                 // persistent blocks (<=148 SMs, 1 CTA/SM)

typedef unsigned long long u64;

// ================= baseline-PTX helpers (family-safe) =====
__device__ __forceinline__ uint32_t smem_u32(const void* p) {
    uint32_t a;
    asm("{ .reg .u64 t; cvta.to.shared.u64 t, %1; cvt.u32.u64 %0, t; }" : "=r"(a) : "l"(p));
    return a;
}
__device__ __forceinline__ void cpasync16(uint32_t s, const void* g) {
    asm volatile("cp.async.ca.shared.global [%0], [%1], 16;" :: "r"(s), "l"(g));
}
#define CP_COMMIT()  asm volatile("cp.async.commit_group;" ::: "memory")
#define CP_WAIT(n)   asm volatile("cp.async.wait_group %0;" :: "n"(n) : "memory")

__device__ __forceinline__ void ldsm4(uint32_t& r0, uint32_t& r1, uint32_t& r2, uint32_t& r3,
                                      uint32_t addr) {
    asm volatile("ldmatrix.sync.aligned.m8n8.x4.shared.b16 {%0,%1,%2,%3}, [%4];"
        : "=r"(r0), "=r"(r1), "=r"(r2), "=r"(r3) : "r"(addr));
}
__device__ __forceinline__ void mma16816(float* c, const uint32_t* a, const uint32_t* b) {
    asm volatile("mma.sync.aligned.m16n8k16.row.col.f32.bf16.bf16.f32 "
        "{%0,%1,%2,%3}, {%4,%5,%6,%7}, {%8,%9}, {%0,%1,%2,%3};"
        : "+f"(c[0]), "+f"(c[1]), "+f"(c[2]), "+f"(c[3])
        : "r"(a[0]), "r"(a[1]), "r"(a[2]), "r"(a[3]), "r"(b[0]), "r"(b[1]));
}
// packed fp32x2 (exact per-lane fp32)
__device__ __forceinline__ u64 pk2(float x) {
    u64 r; asm("mov.b64 %0, {%1, %1};" : "=l"(r) : "f"(x)); return r;
}
__device__ __forceinline__ void fma2(u64& d, u64 a, u64 b) {
    asm("fma.rn.f32x2 %0, %1, %2, %3;" : "=l"(d) : "l"(a), "l"(b), "l"(d));
}
__device__ __forceinline__ float2 upk(u64 v) {
    float2 f; asm("mov.b64 {%0, %1}, %2;" : "=f"(f.x), "=f"(f.y) : "l"(v)); return f;
}
// barrier primitives
__device__ __forceinline__ int ld_acq(const int* p) {
    int v; asm volatile("ld.acquire.gpu.b32 %0, [%1];" : "=r"(v) : "l"(p)); return v;
}
__device__ __forceinline__ void st_rel(int* p, int v) {
    asm volatile("st.release.gpu.b32 [%0], %1;" :: "l"(p), "r"(v));
}
__device__ __forceinline__ void red_addf(float* p, float v) {
    asm volatile("red.global.add.f32 [%0], %1;" :: "l"(p), "f"(v));
}

// ================= device scratch =================
__device__ float g_cent[KC*DM];
__device__ float g_sums[KC*DM];
__device__ int   g_counts[KC];
__device__ float g_centsq[KC];
__device__ int   g_done;
__device__ float g_shift;
__device__ int   g_c1;   // all-blocks barrier counter (monotonic)
__device__ int   g_r1;   // all-blocks release word
__device__ int   g_c2;   // owner (KC) barrier counter
__device__ int   g_r2;   // owner barrier release
// bf16 split matrices
__device__ __nv_bfloat16 g_Ah[NROWS*SEQ];
__device__ __nv_bfloat16 g_Al[NROWS*SEQ];
__device__ __nv_bfloat16 g_Wh[DM*SEQ];
__device__ __nv_bfloat16 g_Wl[DM*SEQ];

// ================= fused prep: init + splitW + splitX =================
union BPack { __nv_bfloat16 h[8]; uint4 u; };

__global__ __launch_bounds__(256) void prep_k(
    const float* __restrict__ x, const float* __restrict__ W,
    const float* __restrict__ centroids)
{
    __shared__ float xs[64][65];
    const int t = threadIdx.x;
    const int flat = blockIdx.y * gridDim.x + blockIdx.x;

    // ---- init slice (flat < 128) ----
    if (flat < 128) {
        int i = flat * 256 + t;
        if (i == 0) {
            g_done = 0; g_shift = 0.f;
            g_c1 = 0; g_r1 = 0; g_c2 = 0; g_r2 = 0;
        }
        if (i < KC) g_counts[i] = 0;
        g_cent[i] = centroids[i];
        g_sums[i] = 0.f;
    }
    // ---- splitW slice (flat < 512) ----
    if (flat < 512) {
        int i = (flat * 256 + t) * 8;
        BPack ph, pl;
        #pragma unroll
        for (int j = 0; j < 8; j++) {
            float f = W[i + j];
            __nv_bfloat16 h = __float2bfloat16(f);
            ph.h[j] = h;
            pl.h[j] = __float2bfloat16(f - __bfloat162float(h));
        }
        *(uint4*)&g_Wh[i] = ph.u;
        *(uint4*)&g_Wl[i] = pl.u;
    }

    // ---- splitX (all 128x32 blocks) ----
    const int b  = blockIdx.x;
    const int s0 = blockIdx.y * 64;
    const float* xp = x + ((size_t)b * SEQ + s0) * NV;
    int v = t & 63, i0 = t >> 6;
    #pragma unroll
    for (int j = 0; j < 16; j++)
        xs[i0 + j*4][v] = xp[(size_t)(i0 + j*4) * NV + v];
    __syncthreads();
    #pragma unroll
    for (int kx = 0; kx < 2; kx++) {
        int w = t + kx * 256;
        int v2 = w >> 3, seg = w & 7;
        BPack ph, pl;
        #pragma unroll
        for (int j = 0; j < 8; j++) {
            float f = xs[seg*8 + j][v2];
            __nv_bfloat16 h = __float2bfloat16(f);
            ph.h[j] = h;
            pl.h[j] = __float2bfloat16(f - __bfloat162float(h));
        }
        size_t off = (size_t)(b*64 + v2) * SEQ + s0 + seg*8;
        *(uint4*)&g_Ah[off] = ph.u;
        *(uint4*)&g_Al[off] = pl.u;
    }
}

// ================= HMMA GEMM (unchanged: ~155us, tensor 55%) ====
#define ASTRIDE 80
#define TILE_B  (128*ASTRIDE)
#define BUF_B   (4*TILE_B)
#define SM_GEMM (2*BUF_B)

__global__ __launch_bounds__(256, 2) void mma_gemm_k(
    const float* __restrict__ bias, float* __restrict__ xe)
{
    extern __shared__ char smem[];
    const uint32_t sb = smem_u32(smem);
    const int t = threadIdx.x;
    const int wid = t >> 5, lane = t & 31;
    const int n0 = blockIdx.y * 128, d0 = blockIdx.x * 128;
    const int wm = wid >> 2, wn = wid & 3;

    const __nv_bfloat16* gm[4] = {
        g_Ah + (size_t)n0 * SEQ, g_Al + (size_t)n0 * SEQ,
        g_Wh + (size_t)d0 * SEQ, g_Wl + (size_t)d0 * SEQ };

    float acc[4][4][4] = {};

    const uint32_t aoff = (uint32_t)(wm*64 + (lane & 15)) * ASTRIDE + (lane >> 4) * 16;
    const uint32_t boff = (uint32_t)(wn*32 + ((lane >> 4) << 3) + (lane & 7)) * ASTRIDE
                        + (((lane >> 3) & 1) * 16);

    auto stage = [&](int ch, int buf) {
        const int s0 = ch * 32;
        const uint32_t bb = sb + buf * BUF_B;
        #pragma unroll
        for (int m = 0; m < 4; m++) {
            const __nv_bfloat16* g = gm[m];
            const uint32_t sm = bb + m * TILE_B;
            int r0 = t >> 2,        c0 = t & 3;
            int r1 = (t+256) >> 2,  c1 = (t+256) & 3;
            cpasync16(sm + r0*ASTRIDE + c0*16, g + (size_t)r0 * SEQ + s0 + c0*8);
            cpasync16(sm + r1*ASTRIDE + c1*16, g + (size_t)r1 * SEQ + s0 + c1*8);
        }
        CP_COMMIT();
    };

    stage(0, 0);
    for (int ch = 0; ch < SEQ/32; ch++) {
        const int buf = ch & 1;
        const bool more = (ch + 1) < SEQ/32;
        if (more) { stage(ch + 1, buf ^ 1); CP_WAIT(1); }
        else      { CP_WAIT(0); }
        __syncthreads();

        const uint32_t bb = sb + buf * BUF_B;
        #pragma unroll
        for (int ks = 0; ks < 2; ks++) {
            const uint32_t ko = ks * 32;
            uint32_t Ah[4][4], Al[4][4], Bh[2][4], Bl[2][4];
            #pragma unroll
            for (int mf = 0; mf < 4; mf++)
                ldsm4(Ah[mf][0], Ah[mf][1], Ah[mf][2], Ah[mf][3],
                      bb + 0*TILE_B + aoff + mf*16*ASTRIDE + ko);
            #pragma unroll
            for (int p = 0; p < 2; p++)
                ldsm4(Bh[p][0], Bh[p][1], Bh[p][2], Bh[p][3],
                      bb + 2*TILE_B + boff + p*16*ASTRIDE + ko);
            #pragma unroll
            for (int mf = 0; mf < 4; mf++)
                #pragma unroll
                for (int nf = 0; nf < 4; nf++)
                    mma16816(acc[mf][nf], Ah[mf], &Bh[nf>>1][(nf&1)*2]);
            #pragma unroll
            for (int mf = 0; mf < 4; mf++)
                ldsm4(Al[mf][0], Al[mf][1], Al[mf][2], Al[mf][3],
                      bb + 1*TILE_B + aoff + mf*16*ASTRIDE + ko);
            #pragma unroll
            for (int mf = 0; mf < 4; mf++)
                #pragma unroll
                for (int nf = 0; nf < 4; nf++)
                    mma16816(acc[mf][nf], Al[mf], &Bh[nf>>1][(nf&1)*2]);
            #pragma unroll
            for (int p = 0; p < 2; p++)
                ldsm4(Bl[p][0], Bl[p][1], Bl[p][2], Bl[p][3],
                      bb + 3*TILE_B + boff + p*16*ASTRIDE + ko);
            #pragma unroll
            for (int mf = 0; mf < 4; mf++)
                #pragma unroll
                for (int nf = 0; nf < 4; nf++)
                    mma16816(acc[mf][nf], Ah[mf], &Bl[nf>>1][(nf&1)*2]);
        }
        __syncthreads();
    }

    const int tg = lane >> 2, tq = lane & 3;
    #pragma unroll
    for (int mf = 0; mf < 4; mf++) {
        const int r0 = n0 + wm*64 + mf*16 + tg;
        #pragma unroll
        for (int nf = 0; nf < 4; nf++) {
            const int c0 = d0 + wn*32 + nf*8 + tq*2;
            const float2 bv = *(const float2*)(bias + c0);
            float2 o0 = make_float2(acc[mf][nf][0] + bv.x, acc[mf][nf][1] + bv.y);
            float2 o1 = make_float2(acc[mf][nf][2] + bv.x, acc[mf][nf][3] + bv.y);
            *(float2*)(xe + (size_t)r0      * DM + c0) = o0;
            *(float2*)(xe + (size_t)(r0+8)  * DM + c0) = o1;
        }
    }
}

// ================= persistent k-means =================
#define XIDX(s) ((s)*68 + (((s) >> 7) << 2))
#define XET_FLOATS 34832
#define CSL 2180
#define POOL_FLOATS (4*CSL)
#define SM_KM ((XET_FLOATS + POOL_FLOATS)*4)   // 174208 B

__device__ __forceinline__ void barrier_all(int inst) {
    __threadfence();
    __syncthreads();
    if (threadIdx.x == 0) {
        int old = atomicAdd(&g_c1, 1);
        if (old == inst * NB - 1) st_rel(&g_r1, inst);
        while (ld_acq(&g_r1) < inst) { }
    }
    __syncthreads();
}

__global__ __launch_bounds__(256, 1) void kmeans_k(
    const float* __restrict__ xe, float* __restrict__ out)
{
    extern __shared__ float dsm[];
    float* xeT  = dsm;
    float* pool = dsm + XET_FLOATS;
    __shared__ int   sids[64];
    __shared__ int   cnts[KC];
    __shared__ int   soff[KC];
    __shared__ int   scopy[KC];
    __shared__ int   sord[64];
    __shared__ int   wtot[2];
    __shared__ float sxq[64];

    const int t    = threadIdx.x;
    const int blk  = blockIdx.x;
    const int n0   = blk * 64;
    const int lane = t & 31, w = t >> 5;
    int ab = 0;

    // ---- pre-phase: xsq (smem), centsq, stage xeT ----
    {
        int row4 = t >> 2, part = t & 3;
        const float* xr = xe + (size_t)(n0 + row4) * DM + part * 128;
        float s = 0.f;
        #pragma unroll
        for (int q = 0; q < 32; q++) {
            float4 v = *(const float4*)(xr + q*4);
            s += v.x*v.x + v.y*v.y + v.z*v.z + v.w*v.w;
        }
        s += __shfl_xor_sync(~0u, s, 1);
        s += __shfl_xor_sync(~0u, s, 2);
        if (part == 0) sxq[row4] = s;

        if (blk < KC) {
            float c1 = __ldcg(&g_cent[blk*DM + t]);
            float c2 = __ldcg(&g_cent[blk*DM + 256 + t]);
            pool[t] = c1*c1 + c2*c2;
            __syncthreads();
            for (int o = 128; o; o >>= 1) { if (t < o) pool[t] += pool[t+o]; __syncthreads(); }
            if (t == 0) g_centsq[blk] = pool[0];
        }

        const int row = t & 63, s4b = t >> 6;
        #pragma unroll
        for (int j = 0; j < 32; j++) {
            int s4 = s4b + j*4;
            float4 v = *(const float4*)(xe + (size_t)(n0+row)*DM + s4*4);
            xeT[XIDX(s4*4+0)+row] = v.x;
            xeT[XIDX(s4*4+1)+row] = v.y;
            xeT[XIDX(s4*4+2)+row] = v.z;
            xeT[XIDX(s4*4+3)+row] = v.w;
        }
        __syncthreads();
    }
    barrier_all(++ab);

    // phase-A mapping: split-K=4, 8x8 tiles
    const int ks = lane & 3;
    const int pidx = lane >> 2;
    const int perm8[8] = {0, 2, 4, 6, 1, 3, 5, 7};
    const int tc = perm8[pidx];
    const int r0 = w * 8;
    const int c0 = tc * 8;

    for (int it = 0; it < MAX_ITER; it++) {
        if (__ldcg(&g_done)) break;

        // ---------- PHASE A: assign (split-K f32x2 GEMM) ----------
        {
            u64 acc[8][4] = {};
            const int crow = t & 63, q = t >> 6;
            for (int c = 0; c < 4; c++) {
                #pragma unroll
                for (int ksl = 0; ksl < 4; ksl++) {
                    float* base = pool + ksl * CSL;
                    #pragma unroll
                    for (int j = 0; j < 2; j++) {
                        int q4 = q + j*4;
                        float4 wv = __ldcg((const float4*)(g_cent
                                      + crow*DM + ksl*128 + c*32 + q4*4));
                        base[(q4*4+0)*68 + crow] = wv.x;
                        base[(q4*4+1)*68 + crow] = wv.y;
                        base[(q4*4+2)*68 + crow] = wv.z;
                        base[(q4*4+3)*68 + crow] = wv.w;
                    }
                }
                __syncthreads();
                const float* cb0 = pool + ks * CSL;
                #pragma unroll 4
                for (int i = 0; i < 32; i++) {
                    int gs = ks*128 + c*32 + i;
                    const float* xr = &xeT[XIDX(gs) + r0];
                    float4 a0 = *(const float4*)xr;
                    float4 a1 = *(const float4*)(xr + 4);
                    const float* cb = cb0 + i*68 + c0;
                    ulonglong2 b0 = *(const ulonglong2*)cb;
                    ulonglong2 b1 = *(const ulonglong2*)(cb + 4);
                    float av[8] = {a0.x, a0.y, a0.z, a0.w, a1.x, a1.y, a1.z, a1.w};
                    u64 bv[4] = {b0.x, b0.y, b1.x, b1.y};
                    #pragma unroll
                    for (int r = 0; r < 8; r++) {
                        u64 ap = pk2(av[r]);
                        fma2(acc[r][0], ap, bv[0]);
                        fma2(acc[r][1], ap, bv[1]);
                        fma2(acc[r][2], ap, bv[2]);
                        fma2(acc[r][3], ap, bv[3]);
                    }
                }
                __syncthreads();
            }

            float cq[8];
            #pragma unroll
            for (int j = 0; j < 8; j++) cq[j] = __ldcg(&g_centsq[c0 + j]);
            float* ds = pool;
            #pragma unroll
            for (int r = 0; r < 8; r++) {
                float res[8];
                #pragma unroll
                for (int j = 0; j < 4; j++) {
                    u64 v = acc[r][j];
                    u64 o = __shfl_xor_sync(~0u, v, 1);
                    float2 f = upk(v), g2 = upk(o);
                    f.x += g2.x; f.y += g2.y;
                    f.x += __shfl_xor_sync(~0u, f.x, 2);
                    f.y += __shfl_xor_sync(~0u, f.y, 2);
                    res[2*j] = f.x; res[2*j+1] = f.y;
                }
                if ((r >> 1) == ks) {
                    int row = r0 + r;
                    float xq = sxq[row];
                    float4 o0 = make_float4(xq - 2.f*res[0] + cq[0], xq - 2.f*res[1] + cq[1],
                                            xq - 2.f*res[2] + cq[2], xq - 2.f*res[3] + cq[3]);
                    float4 o1 = make_float4(xq - 2.f*res[4] + cq[4], xq - 2.f*res[5] + cq[5],
                                            xq - 2.f*res[6] + cq[6], xq - 2.f*res[7] + cq[7]);
                    *(float4*)&ds[row*68 + c0]     = o0;
                    *(float4*)&ds[row*68 + c0 + 4] = o1;
                }
            }
            __syncthreads();
            if (t < 64) {
                float best = 3.4e38f; int bid = 0;
                #pragma unroll 8
                for (int k = 0; k < KC; k++) {
                    float v = ds[t*68 + k];
                    if (v < best) { best = v; bid = k; }
                }
                sids[t] = bid;
            }
            __syncthreads();
        }

        // ---------- PHASE B: counting-sort rows, segment-aggregated RED ----------
        {
            if (t < KC) cnts[t] = 0;
            __syncthreads();
            if (t < 64) atomicAdd(&cnts[sids[t]], 1);
            __syncthreads();
            // exclusive prefix over 64 cluster counts (2-warp shfl scan)
            if (t < 64) {
                int v = cnts[t];
                int inc = v;
                #pragma unroll
                for (int o = 1; o < 32; o <<= 1) {
                    int u = __shfl_up_sync(~0u, inc, o);
                    if (lane >= o) inc += u;
                }
                soff[t] = inc - v;
                if (lane == 31) wtot[t >> 5] = inc;
            }
            __syncthreads();
            if (t >= 32 && t < 64) soff[t] += wtot[0];
            if (t < KC) scopy[t] = (t < 32) ? soff[t] : soff[t] ;  // copy below after fix
            __syncthreads();
            if (t < KC) scopy[t] = soff[t];
            __syncthreads();
            if (t < 64) { int p = atomicAdd(&scopy[sids[t]], 1); sord[p] = t; }
            __syncthreads();

            // segment walk: one RED pair per distinct cluster
            const int d2 = t * 2;
            {
                int rfirst = sord[0];
                int cur = sids[rfirst];
                float2 accv = *(const float2*)(xe + (size_t)(n0+rfirst)*DM + d2);
                #pragma unroll 4
                for (int j = 1; j < 64; j++) {
                    int r = sord[j];
                    int id = sids[r];
                    float2 v = *(const float2*)(xe + (size_t)(n0+r)*DM + d2);
                    if (id != cur) {
                        float* dst = g_sums + cur*DM + d2;
                        red_addf(dst,     accv.x);
                        red_addf(dst + 1, accv.y);
                        accv = v; cur = id;
                    } else {
                        accv.x += v.x; accv.y += v.y;
                    }
                }
                float* dst = g_sums + cur*DM + d2;
                red_addf(dst,     accv.x);
                red_addf(dst + 1, accv.y);
            }
            __syncthreads();
            if (t < KC && cnts[t]) atomicAdd(&g_counts[t], cnts[t]);
        }
        barrier_all(++ab);

        // ---------- PHASE C: owners update centroids; last owner decides ----------
        if (blk < KC) {
            const int k = blk;
            float cnt = (float)__ldcg(&g_counts[k]);
            float inv = 1.f / fmaxf(cnt, 1.f);
            bool  has = cnt > 0.f;
            float sh = 0.f, cq = 0.f;
            #pragma unroll
            for (int j = 0; j < 2; j++) {
                int e = k*DM + t + j*256;
                float old = g_cent[e];
                float nc  = has ? __ldcg(&g_sums[e]) * inv : old;
                g_cent[e] = nc;
                g_sums[e] = 0.f;
                float dd = nc - old;
                sh += dd*dd;
                cq += nc*nc;
            }
            pool[t] = sh; pool[256 + t] = cq;
            __syncthreads();
            for (int o = 128; o; o >>= 1) {
                if (t < o) { pool[t] += pool[t+o]; pool[256+t] += pool[256+t+o]; }
                __syncthreads();
            }
            if (t == 0) {
                g_centsq[k] = pool[256];
                atomicAdd(&g_shift, pool[0]);
                g_counts[k] = 0;
                __threadfence();
                int old = atomicAdd(&g_c2, 1);
                if (old == (it + 1) * KC - 1) {
                    float tot = atomicAdd(&g_shift, 0.f);
                    if (sqrtf(tot) < TOL) g_done = 1;
                    g_shift = 0.f;
                    __threadfence();
                    st_rel(&g_r2, it + 1);
                }
            }
        }
        if (t == 0) { while (ld_acq(&g_r2) < it + 1) { } }
        __syncthreads();
    }

    // ---------- finalize: prob one-hot + cent copy ----------
    for (int i = t; i < 1024; i += 256) {
        int row = i >> 4, kq = (i & 15) << 2;
        int id = sids[row];
        float4 o = make_float4(kq+0 == id ? 1.f : 0.f, kq+1 == id ? 1.f : 0.f,
                               kq+2 == id ? 1.f : 0.f, kq+3 == id ? 1.f : 0.f);
        *(float4*)(out + (size_t)(n0+row)*KC + kq) = o;
    }
    if (blk < KC) {
        #pragma unroll
        for (int i = t; i < 128; i += 256) {
            float4 c = *(const float4*)(g_cent + blk*DM + i*4);
            *(float4*)(out + PROB_ELEMS + blk*DM + i*4) = c;
        }
    }
}

// ================= launch =================
extern "C" void kernel_launch(void* const* d_in, const int* in_sizes, int n_in,
                              void* d_out, int out_size) {
    const float* x         = (const float*)d_in[0];
    const float* W         = (const float*)d_in[1];
    const float* bias      = (const float*)d_in[2];
    const float* centroids = (const float*)d_in[3];
    float* out = (float*)d_out;
    float* xe  = out + PROB_ELEMS + CENT_ELEMS;   // x_emb straight to output

    cudaFuncSetAttribute(mma_gemm_k, cudaFuncAttributeMaxDynamicSharedMemorySize, SM_GEMM);
    cudaFuncSetAttribute(kmeans_k,   cudaFuncAttributeMaxDynamicSharedMemorySize, SM_KM);

    prep_k<<<dim3(BS, SEQ/64), 256>>>(x, W, centroids);
    mma_gemm_k<<<dim3(DM/128, NROWS/128), 256, SM_GEMM>>>(bias, xe);
    kmeans_k<<<NB, 256, SM_KM>>>(xe, out);
}

// round 16
// speedup vs baseline: 3.6000x; 1.3345x over previous
#include <cuda_runtime.h>
#include <cuda_bf16.h>
#include <cstdint>

#define BS 128
#define SEQ 2048
#define NV 64
#define DM 512
#define KC 64
#define NROWS (BS*NV)          // 8192
#define MAX_ITER 10
#define TOL 1e-4f
#define PROB_ELEMS (BS*NV*KC)  // 524288
#define CENT_ELEMS (KC*DM)     // 32768
#define NB 128                 // persistent blocks (<=148 SMs, 1 CTA/SM)

typedef unsigned long long u64;

// ================= baseline-PTX helpers (family-safe) =====
__device__ __forceinline__ uint32_t smem_u32(const void* p) {
    uint32_t a;
    asm("{ .reg .u64 t; cvta.to.shared.u64 t, %1; cvt.u32.u64 %0, t; }" : "=r"(a) : "l"(p));
    return a;
}
__device__ __forceinline__ void cpasync16(uint32_t s, const void* g) {
    asm volatile("cp.async.ca.shared.global [%0], [%1], 16;" :: "r"(s), "l"(g));
}
__device__ __forceinline__ void cpasync_cg16(uint32_t s, const void* g) {
    asm volatile("cp.async.cg.shared.global [%0], [%1], 16;" :: "r"(s), "l"(g));
}
#define CP_COMMIT()  asm volatile("cp.async.commit_group;" ::: "memory")
#define CP_WAIT(n)   asm volatile("cp.async.wait_group %0;" :: "n"(n) : "memory")

__device__ __forceinline__ void ldsm4(uint32_t& r0, uint32_t& r1, uint32_t& r2, uint32_t& r3,
                                      uint32_t addr) {
    asm volatile("ldmatrix.sync.aligned.m8n8.x4.shared.b16 {%0,%1,%2,%3}, [%4];"
        : "=r"(r0), "=r"(r1), "=r"(r2), "=r"(r3) : "r"(addr));
}
__device__ __forceinline__ void mma16816(float* c, const uint32_t* a, const uint32_t* b) {
    asm volatile("mma.sync.aligned.m16n8k16.row.col.f32.bf16.bf16.f32 "
        "{%0,%1,%2,%3}, {%4,%5,%6,%7}, {%8,%9}, {%0,%1,%2,%3};"
        : "+f"(c[0]), "+f"(c[1]), "+f"(c[2]), "+f"(c[3])
        : "r"(a[0]), "r"(a[1]), "r"(a[2]), "r"(a[3]), "r"(b[0]), "r"(b[1]));
}
// barrier primitives
__device__ __forceinline__ int ld_acq(const int* p) {
    int v; asm volatile("ld.acquire.gpu.b32 %0, [%1];" : "=r"(v) : "l"(p)); return v;
}
__device__ __forceinline__ void st_rel(int* p, int v) {
    asm volatile("st.release.gpu.b32 [%0], %1;" :: "l"(p), "r"(v));
}
__device__ __forceinline__ void red_addf(float* p, float v) {
    asm volatile("red.global.add.f32 [%0], %1;" :: "l"(p), "f"(v));
}

// ================= device scratch =================
__device__ float g_cent[KC*DM];
__device__ float g_sums[KC*DM];
__device__ int   g_counts[KC];
__device__ float g_centsq[KC];
__device__ int   g_done;
__device__ float g_shift;
__device__ int   g_c1;
__device__ int   g_r1;
__device__ int   g_c2;
__device__ int   g_r2;
// bf16 split matrices (gemm) + bf16 split centroids (kmeans phase A)
__device__ __nv_bfloat16 g_Ah[NROWS*SEQ];
__device__ __nv_bfloat16 g_Al[NROWS*SEQ];
__device__ __nv_bfloat16 g_Wh[DM*SEQ];
__device__ __nv_bfloat16 g_Wl[DM*SEQ];
__device__ __nv_bfloat16 g_centh[KC*DM];
__device__ __nv_bfloat16 g_centl[KC*DM];

// ================= fused prep: init + splitW + splitX =================
union BPack { __nv_bfloat16 h[8]; uint4 u; };

__global__ __launch_bounds__(256) void prep_k(
    const float* __restrict__ x, const float* __restrict__ W,
    const float* __restrict__ centroids)
{
    __shared__ float xs[64][65];
    const int t = threadIdx.x;
    const int flat = blockIdx.y * gridDim.x + blockIdx.x;

    if (flat < 128) {
        int i = flat * 256 + t;
        if (i == 0) {
            g_done = 0; g_shift = 0.f;
            g_c1 = 0; g_r1 = 0; g_c2 = 0; g_r2 = 0;
        }
        if (i < KC) g_counts[i] = 0;
        g_cent[i] = centroids[i];
        g_sums[i] = 0.f;
    }
    if (flat < 512) {
        int i = (flat * 256 + t) * 8;
        BPack ph, pl;
        #pragma unroll
        for (int j = 0; j < 8; j++) {
            float f = W[i + j];
            __nv_bfloat16 h = __float2bfloat16(f);
            ph.h[j] = h;
            pl.h[j] = __float2bfloat16(f - __bfloat162float(h));
        }
        *(uint4*)&g_Wh[i] = ph.u;
        *(uint4*)&g_Wl[i] = pl.u;
    }

    const int b  = blockIdx.x;
    const int s0 = blockIdx.y * 64;
    const float* xp = x + ((size_t)b * SEQ + s0) * NV;
    int v = t & 63, i0 = t >> 6;
    #pragma unroll
    for (int j = 0; j < 16; j++)
        xs[i0 + j*4][v] = xp[(size_t)(i0 + j*4) * NV + v];
    __syncthreads();
    #pragma unroll
    for (int kx = 0; kx < 2; kx++) {
        int w = t + kx * 256;
        int v2 = w >> 3, seg = w & 7;
        BPack ph, pl;
        #pragma unroll
        for (int j = 0; j < 8; j++) {
            float f = xs[seg*8 + j][v2];
            __nv_bfloat16 h = __float2bfloat16(f);
            ph.h[j] = h;
            pl.h[j] = __float2bfloat16(f - __bfloat162float(h));
        }
        size_t off = (size_t)(b*64 + v2) * SEQ + s0 + seg*8;
        *(uint4*)&g_Ah[off] = ph.u;
        *(uint4*)&g_Al[off] = pl.u;
    }
}

// ================= HMMA GEMM (unchanged: ~155us, tensor 55%) ====
#define ASTRIDE 80
#define TILE_B  (128*ASTRIDE)
#define BUF_B   (4*TILE_B)
#define SM_GEMM (2*BUF_B)

__global__ __launch_bounds__(256, 2) void mma_gemm_k(
    const float* __restrict__ bias, float* __restrict__ xe)
{
    extern __shared__ char smem[];
    const uint32_t sb = smem_u32(smem);
    const int t = threadIdx.x;
    const int wid = t >> 5, lane = t & 31;
    const int n0 = blockIdx.y * 128, d0 = blockIdx.x * 128;
    const int wm = wid >> 2, wn = wid & 3;

    const __nv_bfloat16* gm[4] = {
        g_Ah + (size_t)n0 * SEQ, g_Al + (size_t)n0 * SEQ,
        g_Wh + (size_t)d0 * SEQ, g_Wl + (size_t)d0 * SEQ };

    float acc[4][4][4] = {};

    const uint32_t aoff = (uint32_t)(wm*64 + (lane & 15)) * ASTRIDE + (lane >> 4) * 16;
    const uint32_t boff = (uint32_t)(wn*32 + ((lane >> 4) << 3) + (lane & 7)) * ASTRIDE
                        + (((lane >> 3) & 1) * 16);

    auto stage = [&](int ch, int buf) {
        const int s0 = ch * 32;
        const uint32_t bb = sb + buf * BUF_B;
        #pragma unroll
        for (int m = 0; m < 4; m++) {
            const __nv_bfloat16* g = gm[m];
            const uint32_t sm = bb + m * TILE_B;
            int r0 = t >> 2,        c0 = t & 3;
            int r1 = (t+256) >> 2,  c1 = (t+256) & 3;
            cpasync16(sm + r0*ASTRIDE + c0*16, g + (size_t)r0 * SEQ + s0 + c0*8);
            cpasync16(sm + r1*ASTRIDE + c1*16, g + (size_t)r1 * SEQ + s0 + c1*8);
        }
        CP_COMMIT();
    };

    stage(0, 0);
    for (int ch = 0; ch < SEQ/32; ch++) {
        const int buf = ch & 1;
        const bool more = (ch + 1) < SEQ/32;
        if (more) { stage(ch + 1, buf ^ 1); CP_WAIT(1); }
        else      { CP_WAIT(0); }
        __syncthreads();

        const uint32_t bb = sb + buf * BUF_B;
        #pragma unroll
        for (int ks = 0; ks < 2; ks++) {
            const uint32_t ko = ks * 32;
            uint32_t Ah[4][4], Al[4][4], Bh[2][4], Bl[2][4];
            #pragma unroll
            for (int mf = 0; mf < 4; mf++)
                ldsm4(Ah[mf][0], Ah[mf][1], Ah[mf][2], Ah[mf][3],
                      bb + 0*TILE_B + aoff + mf*16*ASTRIDE + ko);
            #pragma unroll
            for (int p = 0; p < 2; p++)
                ldsm4(Bh[p][0], Bh[p][1], Bh[p][2], Bh[p][3],
                      bb + 2*TILE_B + boff + p*16*ASTRIDE + ko);
            #pragma unroll
            for (int mf = 0; mf < 4; mf++)
                #pragma unroll
                for (int nf = 0; nf < 4; nf++)
                    mma16816(acc[mf][nf], Ah[mf], &Bh[nf>>1][(nf&1)*2]);
            #pragma unroll
            for (int mf = 0; mf < 4; mf++)
                ldsm4(Al[mf][0], Al[mf][1], Al[mf][2], Al[mf][3],
                      bb + 1*TILE_B + aoff + mf*16*ASTRIDE + ko);
            #pragma unroll
            for (int mf = 0; mf < 4; mf++)
                #pragma unroll
                for (int nf = 0; nf < 4; nf++)
                    mma16816(acc[mf][nf], Al[mf], &Bh[nf>>1][(nf&1)*2]);
            #pragma unroll
            for (int p = 0; p < 2; p++)
                ldsm4(Bl[p][0], Bl[p][1], Bl[p][2], Bl[p][3],
                      bb + 3*TILE_B + boff + p*16*ASTRIDE + ko);
            #pragma unroll
            for (int mf = 0; mf < 4; mf++)
                #pragma unroll
                for (int nf = 0; nf < 4; nf++)
                    mma16816(acc[mf][nf], Ah[mf], &Bl[nf>>1][(nf&1)*2]);
        }
        __syncthreads();
    }

    const int tg = lane >> 2, tq = lane & 3;
    #pragma unroll
    for (int mf = 0; mf < 4; mf++) {
        const int r0 = n0 + wm*64 + mf*16 + tg;
        #pragma unroll
        for (int nf = 0; nf < 4; nf++) {
            const int c0 = d0 + wn*32 + nf*8 + tq*2;
            const float2 bv = *(const float2*)(bias + c0);
            float2 o0 = make_float2(acc[mf][nf][0] + bv.x, acc[mf][nf][1] + bv.y);
            float2 o1 = make_float2(acc[mf][nf][2] + bv.x, acc[mf][nf][3] + bv.y);
            *(float2*)(xe + (size_t)r0      * DM + c0) = o0;
            *(float2*)(xe + (size_t)(r0+8)  * DM + c0) = o1;
        }
    }
}

// ================= persistent k-means (phase A on HMMA) =================
// dyn smem layout (bytes):
//   0       : xebh  16 chunks x (64 rows x 80B)  = 81920   (xe rows, bf16 hi)
//   81920   : xebl  81920                                   (bf16 lo)
//   163840  : cb    2 slots x (hi 5120 + lo 5120) = 20480   (cent chunk buffers)
//   184320  : ds    64 x 68 floats = 17408                  (distances / reductions)
#define XB_H   0
#define XB_L   81920
#define CB     163840
#define DS_OFF 184320
#define SM_KM  201728
#define CCH    5120            // one cent chunk tile (64 rows x 80B)

__device__ __forceinline__ void barrier_all(int inst) {
    __threadfence();
    __syncthreads();
    if (threadIdx.x == 0) {
        int old = atomicAdd(&g_c1, 1);
        if (old == inst * NB - 1) st_rel(&g_r1, inst);
        while (ld_acq(&g_r1) < inst) { }
    }
    __syncthreads();
}

__global__ __launch_bounds__(256, 1) void kmeans_k(
    const float* __restrict__ xe, float* __restrict__ out)
{
    extern __shared__ char smem[];
    const uint32_t sb = smem_u32(smem);
    float* ds = (float*)(smem + DS_OFF);
    __shared__ int   sids[64];
    __shared__ int   cnts[KC];
    __shared__ int   soff[KC];
    __shared__ int   scopy[KC];
    __shared__ int   sord[64];
    __shared__ int   wtot[2];
    __shared__ float sxq[64];

    const int t    = threadIdx.x;
    const int blk  = blockIdx.x;
    const int n0   = blk * 64;
    const int lane = t & 31, w = t >> 5;
    int ab = 0;

    // ---- pre-phase: xsq, owner centsq + bf16 cent, stage xe rows as bf16 hi/lo ----
    {
        int row4 = t >> 2, part = t & 3;
        const float* xr = xe + (size_t)(n0 + row4) * DM + part * 128;
        float s = 0.f;
        #pragma unroll
        for (int q = 0; q < 32; q++) {
            float4 v = *(const float4*)(xr + q*4);
            s += v.x*v.x + v.y*v.y + v.z*v.z + v.w*v.w;
        }
        s += __shfl_xor_sync(~0u, s, 1);
        s += __shfl_xor_sync(~0u, s, 2);
        if (part == 0) sxq[row4] = s;

        if (blk < KC) {
            int e1 = blk*DM + t, e2 = e1 + 256;
            float c1 = __ldcg(&g_cent[e1]);
            float c2 = __ldcg(&g_cent[e2]);
            __nv_bfloat16 h1 = __float2bfloat16(c1);
            __nv_bfloat16 h2 = __float2bfloat16(c2);
            g_centh[e1] = h1; g_centl[e1] = __float2bfloat16(c1 - __bfloat162float(h1));
            g_centh[e2] = h2; g_centl[e2] = __float2bfloat16(c2 - __bfloat162float(h2));
            ds[t] = c1*c1 + c2*c2;
            __syncthreads();
            for (int o = 128; o; o >>= 1) { if (t < o) ds[t] += ds[t+o]; __syncthreads(); }
            if (t == 0) g_centsq[blk] = ds[0];
        }

        // convert 64 xe rows to bf16 hi/lo, chunk-major [ch][row][k32] stride 80B
        #pragma unroll
        for (int j = 0; j < 16; j++) {
            int gi = t + 256*j;
            int row = gi >> 6, grp = gi & 63;
            int ch = grp >> 2, kk = (grp & 3) * 8;
            const float* src = xe + (size_t)(n0+row)*DM + ch*32 + kk;
            float4 v0 = *(const float4*)src;
            float4 v1 = *(const float4*)(src + 4);
            float f[8] = {v0.x, v0.y, v0.z, v0.w, v1.x, v1.y, v1.z, v1.w};
            BPack ph, pl;
            #pragma unroll
            for (int q = 0; q < 8; q++) {
                __nv_bfloat16 h = __float2bfloat16(f[q]);
                ph.h[q] = h;
                pl.h[q] = __float2bfloat16(f[q] - __bfloat162float(h));
            }
            uint32_t off = ch*CCH + row*80 + kk*2;
            *(uint4*)(smem + XB_H + off) = ph.u;
            *(uint4*)(smem + XB_L + off) = pl.u;
        }
        __syncthreads();
    }
    barrier_all(++ab);

    // phase-A HMMA mapping: 8 warps = 4 m-tiles x 2 n-halves
    const int mt = w >> 1, nh = w & 1;
    const uint32_t aoff = (uint32_t)(mt*16 + (lane & 15)) * 80 + (lane >> 4) * 16;
    const uint32_t boff = (uint32_t)(nh*32 + ((lane >> 4) << 3) + (lane & 7)) * 80
                        + (((lane >> 3) & 1) * 16);
    const int tg = lane >> 2, tq = lane & 3;

    for (int it = 0; it < MAX_ITER; it++) {
        if (__ldcg(&g_done)) break;

        // ---------- PHASE A: distances via bf16x3 HMMA ----------
        {
            float acc[4][4] = {};            // [nf][4]
            const int crow = t >> 2, cseg = t & 3;

            auto stageC = [&](int ch, int slot) {
                uint32_t dst = sb + CB + slot*(2*CCH) + crow*80 + cseg*16;
                const char* srch = (const char*)g_centh + crow*1024 + ch*64 + cseg*16;
                const char* srcl = (const char*)g_centl + crow*1024 + ch*64 + cseg*16;
                cpasync_cg16(dst,       srch);
                cpasync_cg16(dst + CCH, srcl);
                CP_COMMIT();
            };

            stageC(0, 0);
            for (int ch = 0; ch < 16; ch++) {
                const int slot = ch & 1;
                const bool more = ch < 15;
                if (more) { stageC(ch + 1, slot ^ 1); CP_WAIT(1); }
                else      { CP_WAIT(0); }
                __syncthreads();

                const uint32_t xh = sb + XB_H + ch*CCH + aoff;
                const uint32_t xl = sb + XB_L + ch*CCH + aoff;
                const uint32_t bh = sb + CB + slot*(2*CCH) + boff;
                const uint32_t bl = bh + CCH;
                #pragma unroll
                for (int kh = 0; kh < 2; kh++) {
                    const uint32_t ko = kh * 32;
                    uint32_t Ah[4], Al[4], Bh[2][4], Bl[2][4];
                    ldsm4(Ah[0], Ah[1], Ah[2], Ah[3], xh + ko);
                    ldsm4(Al[0], Al[1], Al[2], Al[3], xl + ko);
                    ldsm4(Bh[0][0], Bh[0][1], Bh[0][2], Bh[0][3], bh + ko);
                    ldsm4(Bh[1][0], Bh[1][1], Bh[1][2], Bh[1][3], bh + 1280 + ko);
                    ldsm4(Bl[0][0], Bl[0][1], Bl[0][2], Bl[0][3], bl + ko);
                    ldsm4(Bl[1][0], Bl[1][1], Bl[1][2], Bl[1][3], bl + 1280 + ko);
                    #pragma unroll
                    for (int nf = 0; nf < 4; nf++) {
                        mma16816(acc[nf], Ah, &Bh[nf>>1][(nf&1)*2]);
                        mma16816(acc[nf], Ah, &Bl[nf>>1][(nf&1)*2]);
                        mma16816(acc[nf], Al, &Bh[nf>>1][(nf&1)*2]);
                    }
                }
                __syncthreads();
            }

            // distances -> ds
            const int r0 = mt*16 + tg, r1 = r0 + 8;
            const float xq0 = sxq[r0], xq1 = sxq[r1];
            #pragma unroll
            for (int nf = 0; nf < 4; nf++) {
                const int c = nh*32 + nf*8 + tq*2;
                float cs0 = __ldcg(&g_centsq[c]);
                float cs1 = __ldcg(&g_centsq[c+1]);
                ds[r0*68 + c]     = xq0 - 2.f*acc[nf][0] + cs0;
                ds[r0*68 + c + 1] = xq0 - 2.f*acc[nf][1] + cs1;
                ds[r1*68 + c]     = xq1 - 2.f*acc[nf][2] + cs0;
                ds[r1*68 + c + 1] = xq1 - 2.f*acc[nf][3] + cs1;
            }
            __syncthreads();
            if (t < 64) {
                float best = 3.4e38f; int bid = 0;
                #pragma unroll 8
                for (int k = 0; k < KC; k++) {
                    float v = ds[t*68 + k];
                    if (v < best) { best = v; bid = k; }
                }
                sids[t] = bid;
            }
            __syncthreads();
        }

        // ---------- PHASE B: counting-sort rows, segment-aggregated RED ----------
        {
            if (t < KC) cnts[t] = 0;
            __syncthreads();
            if (t < 64) atomicAdd(&cnts[sids[t]], 1);
            __syncthreads();
            if (t < 64) {
                int v = cnts[t];
                int inc = v;
                #pragma unroll
                for (int o = 1; o < 32; o <<= 1) {
                    int u = __shfl_up_sync(~0u, inc, o);
                    if (lane >= o) inc += u;
                }
                soff[t] = inc - v;
                if (lane == 31) wtot[t >> 5] = inc;
            }
            __syncthreads();
            if (t >= 32 && t < 64) soff[t] += wtot[0];
            __syncthreads();
            if (t < KC) scopy[t] = soff[t];
            __syncthreads();
            if (t < 64) { int p = atomicAdd(&scopy[sids[t]], 1); sord[p] = t; }
            __syncthreads();

            const int d2 = t * 2;
            {
                int rfirst = sord[0];
                int cur = sids[rfirst];
                float2 accv = *(const float2*)(xe + (size_t)(n0+rfirst)*DM + d2);
                #pragma unroll 4
                for (int j = 1; j < 64; j++) {
                    int r = sord[j];
                    int id = sids[r];
                    float2 v = *(const float2*)(xe + (size_t)(n0+r)*DM + d2);
                    if (id != cur) {
                        float* dst = g_sums + cur*DM + d2;
                        red_addf(dst,     accv.x);
                        red_addf(dst + 1, accv.y);
                        accv = v; cur = id;
                    } else {
                        accv.x += v.x; accv.y += v.y;
                    }
                }
                float* dst = g_sums + cur*DM + d2;
                red_addf(dst,     accv.x);
                red_addf(dst + 1, accv.y);
            }
            __syncthreads();
            if (t < KC && cnts[t]) atomicAdd(&g_counts[t], cnts[t]);
        }
        barrier_all(++ab);

        // ---------- PHASE C: owners update centroids (+bf16); last owner decides ----------
        if (blk < KC) {
            const int k = blk;
            float cnt = (float)__ldcg(&g_counts[k]);
            float inv = 1.f / fmaxf(cnt, 1.f);
            bool  has = cnt > 0.f;
            float sh = 0.f, cq = 0.f;
            #pragma unroll
            for (int j = 0; j < 2; j++) {
                int e = k*DM + t + j*256;
                float old = g_cent[e];
                float nc  = has ? __ldcg(&g_sums[e]) * inv : old;
                g_cent[e] = nc;
                g_sums[e] = 0.f;
                __nv_bfloat16 h = __float2bfloat16(nc);
                g_centh[e] = h;
                g_centl[e] = __float2bfloat16(nc - __bfloat162float(h));
                float dd = nc - old;
                sh += dd*dd;
                cq += nc*nc;
            }
            ds[t] = sh; ds[256 + t] = cq;
            __syncthreads();
            for (int o = 128; o; o >>= 1) {
                if (t < o) { ds[t] += ds[t+o]; ds[256+t] += ds[256+t+o]; }
                __syncthreads();
            }
            if (t == 0) {
                g_centsq[k] = ds[256];
                atomicAdd(&g_shift, ds[0]);
                g_counts[k] = 0;
                __threadfence();
                int old = atomicAdd(&g_c2, 1);
                if (old == (it + 1) * KC - 1) {
                    float tot = atomicAdd(&g_shift, 0.f);
                    if (sqrtf(tot) < TOL) g_done = 1;
                    g_shift = 0.f;
                    __threadfence();
                    st_rel(&g_r2, it + 1);
                }
            }
        }
        if (t == 0) { while (ld_acq(&g_r2) < it + 1) { } }
        __syncthreads();
    }

    // ---------- finalize: prob one-hot + cent copy ----------
    for (int i = t; i < 1024; i += 256) {
        int row = i >> 4, kq = (i & 15) << 2;
        int id = sids[row];
        float4 o = make_float4(kq+0 == id ? 1.f : 0.f, kq+1 == id ? 1.f : 0.f,
                               kq+2 == id ? 1.f : 0.f, kq+3 == id ? 1.f : 0.f);
        *(float4*)(out + (size_t)(n0+row)*KC + kq) = o;
    }
    if (blk < KC) {
        #pragma unroll
        for (int i = t; i < 128; i += 256) {
            float4 c = *(const float4*)(g_cent + blk*DM + i*4);
            *(float4*)(out + PROB_ELEMS + blk*DM + i*4) = c;
        }
    }
}

// ================= launch =================
extern "C" void kernel_launch(void* const* d_in, const int* in_sizes, int n_in,
                              void* d_out, int out_size) {
    const float* x         = (const float*)d_in[0];
    const float* W         = (const float*)d_in[1];
    const float* bias      = (const float*)d_in[2];
    const float* centroids = (const float*)d_in[3];
    float* out = (float*)d_out;
    float* xe  = out + PROB_ELEMS + CENT_ELEMS;   // x_emb straight to output

    cudaFuncSetAttribute(mma_gemm_k, cudaFuncAttributeMaxDynamicSharedMemorySize, SM_GEMM);
    cudaFuncSetAttribute(kmeans_k,   cudaFuncAttributeMaxDynamicSharedMemorySize, SM_KM);

    prep_k<<<dim3(BS, SEQ/64), 256>>>(x, W, centroids);
    mma_gemm_k<<<dim3(DM/128, NROWS/128), 256, SM_GEMM>>>(bias, xe);
    kmeans_k<<<NB, 256, SM_KM>>>(xe, out);
}

// round 17
// speedup vs baseline: 3.6743x; 1.0206x over previous
#include <cuda_runtime.h>
#include <cuda_bf16.h>
#include <cstdint>

#define BS 128
#define SEQ 2048
#define NV 64
#define DM 512
#define KC 64
#define NROWS (BS*NV)          // 8192
#define MAX_ITER 10
#define TOL 1e-4f
#define PROB_ELEMS (BS*NV*KC)  // 524288
#define CENT_ELEMS (KC*DM)     // 32768
#define NB 128                 // persistent blocks (<=148 SMs, 1 CTA/SM)

typedef unsigned long long u64;

// ================= baseline-PTX helpers (family-safe) =====
__device__ __forceinline__ uint32_t smem_u32(const void* p) {
    uint32_t a;
    asm("{ .reg .u64 t; cvta.to.shared.u64 t, %1; cvt.u32.u64 %0, t; }" : "=r"(a) : "l"(p));
    return a;
}
__device__ __forceinline__ void cpasync16(uint32_t s, const void* g) {
    asm volatile("cp.async.ca.shared.global [%0], [%1], 16;" :: "r"(s), "l"(g));
}
__device__ __forceinline__ void cpasync_cg16(uint32_t s, const void* g) {
    asm volatile("cp.async.cg.shared.global [%0], [%1], 16;" :: "r"(s), "l"(g));
}
#define CP_COMMIT()  asm volatile("cp.async.commit_group;" ::: "memory")
#define CP_WAIT(n)   asm volatile("cp.async.wait_group %0;" :: "n"(n) : "memory")

__device__ __forceinline__ void ldsm4(uint32_t& r0, uint32_t& r1, uint32_t& r2, uint32_t& r3,
                                      uint32_t addr) {
    asm volatile("ldmatrix.sync.aligned.m8n8.x4.shared.b16 {%0,%1,%2,%3}, [%4];"
        : "=r"(r0), "=r"(r1), "=r"(r2), "=r"(r3) : "r"(addr));
}
__device__ __forceinline__ void mma16816(float* c, const uint32_t* a, const uint32_t* b) {
    asm volatile("mma.sync.aligned.m16n8k16.row.col.f32.bf16.bf16.f32 "
        "{%0,%1,%2,%3}, {%4,%5,%6,%7}, {%8,%9}, {%0,%1,%2,%3};"
        : "+f"(c[0]), "+f"(c[1]), "+f"(c[2]), "+f"(c[3])
        : "r"(a[0]), "r"(a[1]), "r"(a[2]), "r"(a[3]), "r"(b[0]), "r"(b[1]));
}
// barrier primitives
__device__ __forceinline__ int ld_acq(const int* p) {
    int v; asm volatile("ld.acquire.gpu.b32 %0, [%1];" : "=r"(v) : "l"(p)); return v;
}
__device__ __forceinline__ void st_rel(int* p, int v) {
    asm volatile("st.release.gpu.b32 [%0], %1;" :: "l"(p), "r"(v));
}
__device__ __forceinline__ void red_addf(float* p, float v) {
    asm volatile("red.global.add.f32 [%0], %1;" :: "l"(p), "f"(v));
}
__device__ __forceinline__ void red_addu(int* p, int v) {
    asm volatile("red.global.add.u32 [%0], %1;" :: "l"(p), "r"(v));
}

// ================= device scratch =================
__device__ float g_cent[KC*DM];
__device__ float g_sums[KC*DM];
__device__ int   g_counts[KC];
__device__ float g_centsq[KC];
__device__ int   g_done;
__device__ float g_shift;
__device__ int   g_c1;
__device__ int   g_r1;
__device__ int   g_c2;
__device__ int   g_r2;
// bf16 split matrices (gemm) + bf16 split centroids (kmeans phase A)
__device__ __nv_bfloat16 g_Ah[NROWS*SEQ];
__device__ __nv_bfloat16 g_Al[NROWS*SEQ];
__device__ __nv_bfloat16 g_Wh[DM*SEQ];
__device__ __nv_bfloat16 g_Wl[DM*SEQ];
__device__ __nv_bfloat16 g_centh[KC*DM];
__device__ __nv_bfloat16 g_centl[KC*DM];

// ================= fused prep: init + splitW + splitX =================
union BPack { __nv_bfloat16 h[8]; uint4 u; };

__global__ __launch_bounds__(256) void prep_k(
    const float* __restrict__ x, const float* __restrict__ W,
    const float* __restrict__ centroids)
{
    __shared__ float xs[64][65];
    const int t = threadIdx.x;
    const int flat = blockIdx.y * gridDim.x + blockIdx.x;

    if (flat < 128) {
        int i = flat * 256 + t;
        if (i == 0) {
            g_done = 0; g_shift = 0.f;
            g_c1 = 0; g_r1 = 0; g_c2 = 0; g_r2 = 0;
        }
        if (i < KC) g_counts[i] = 0;
        g_cent[i] = centroids[i];
        g_sums[i] = 0.f;
    }
    if (flat < 512) {
        int i = (flat * 256 + t) * 8;
        BPack ph, pl;
        #pragma unroll
        for (int j = 0; j < 8; j++) {
            float f = W[i + j];
            __nv_bfloat16 h = __float2bfloat16(f);
            ph.h[j] = h;
            pl.h[j] = __float2bfloat16(f - __bfloat162float(h));
        }
        *(uint4*)&g_Wh[i] = ph.u;
        *(uint4*)&g_Wl[i] = pl.u;
    }

    const int b  = blockIdx.x;
    const int s0 = blockIdx.y * 64;
    const float* xp = x + ((size_t)b * SEQ + s0) * NV;
    int v = t & 63, i0 = t >> 6;
    #pragma unroll
    for (int j = 0; j < 16; j++)
        xs[i0 + j*4][v] = xp[(size_t)(i0 + j*4) * NV + v];
    __syncthreads();
    #pragma unroll
    for (int kx = 0; kx < 2; kx++) {
        int w = t + kx * 256;
        int v2 = w >> 3, seg = w & 7;
        BPack ph, pl;
        #pragma unroll
        for (int j = 0; j < 8; j++) {
            float f = xs[seg*8 + j][v2];
            __nv_bfloat16 h = __float2bfloat16(f);
            ph.h[j] = h;
            pl.h[j] = __float2bfloat16(f - __bfloat162float(h));
        }
        size_t off = (size_t)(b*64 + v2) * SEQ + s0 + seg*8;
        *(uint4*)&g_Ah[off] = ph.u;
        *(uint4*)&g_Al[off] = pl.u;
    }
}

// ================= HMMA GEMM: CTA tile 256x128, warp tile 64x64 =================
// 8 warps as 4(wm) x 2(wn); 1 CTA/SM (255 regs); grid (4, 32) = 128 blocks.
#define G_ASTR  80
#define G_AT    20480              // 256 rows x 80B (one of Ah/Al)
#define G_BT    10240              // 128 rows x 80B (one of Bh/Bl)
#define G_BUF   (2*G_AT + 2*G_BT)  // 61440
#define SM_GEMM (2*G_BUF)          // 122880

__global__ __launch_bounds__(256, 1) void mma_gemm_k(
    const float* __restrict__ bias, float* __restrict__ xe)
{
    extern __shared__ char smem[];
    const uint32_t sb = smem_u32(smem);
    const int t = threadIdx.x;
    const int wid = t >> 5, lane = t & 31;
    const int d0 = blockIdx.x * 128;
    const int n0 = blockIdx.y * 256;
    const int wm = wid >> 1, wn = wid & 1;

    const __nv_bfloat16* gAh = g_Ah + (size_t)n0 * SEQ;
    const __nv_bfloat16* gAl = g_Al + (size_t)n0 * SEQ;
    const __nv_bfloat16* gBh = g_Wh + (size_t)d0 * SEQ;
    const __nv_bfloat16* gBl = g_Wl + (size_t)d0 * SEQ;

    float acc[4][8][4] = {};     // [mf][nf][4] = 128 regs

    const uint32_t aoff = (uint32_t)(wm*64 + (lane & 15)) * G_ASTR + (lane >> 4) * 16;
    const uint32_t boff = (uint32_t)(wn*64 + ((lane >> 4) << 3) + (lane & 7)) * G_ASTR
                        + (((lane >> 3) & 1) * 16);

    auto stage = [&](int ch, int buf) {
        const int s0 = ch * 32;
        const uint32_t bb = sb + buf * G_BUF;
        #pragma unroll
        for (int j = 0; j < 4; j++) {          // A: 1024 16B-units each
            int idx = t + 256*j;
            int row = idx >> 2, seg = idx & 3;
            cpasync16(bb + row*G_ASTR + seg*16,
                      gAh + (size_t)row * SEQ + s0 + seg*8);
            cpasync16(bb + G_AT + row*G_ASTR + seg*16,
                      gAl + (size_t)row * SEQ + s0 + seg*8);
        }
        #pragma unroll
        for (int j = 0; j < 2; j++) {          // B: 512 units each
            int idx = t + 256*j;
            int row = idx >> 2, seg = idx & 3;
            cpasync16(bb + 2*G_AT + row*G_ASTR + seg*16,
                      gBh + (size_t)row * SEQ + s0 + seg*8);
            cpasync16(bb + 2*G_AT + G_BT + row*G_ASTR + seg*16,
                      gBl + (size_t)row * SEQ + s0 + seg*8);
        }
        CP_COMMIT();
    };

    stage(0, 0);
    for (int ch = 0; ch < SEQ/32; ch++) {
        const int buf = ch & 1;
        const bool more = (ch + 1) < SEQ/32;
        if (more) { stage(ch + 1, buf ^ 1); CP_WAIT(1); }
        else      { CP_WAIT(0); }
        __syncthreads();

        const uint32_t bb = sb + buf * G_BUF;
        #pragma unroll
        for (int ks = 0; ks < 2; ks++) {
            const uint32_t ko = ks * 32;
            uint32_t Ah[4][4], Al[4][4], Bh[4][4], Bl[4][4];
            #pragma unroll
            for (int mf = 0; mf < 4; mf++)
                ldsm4(Ah[mf][0], Ah[mf][1], Ah[mf][2], Ah[mf][3],
                      bb + aoff + mf*16*G_ASTR + ko);
            #pragma unroll
            for (int p = 0; p < 4; p++)
                ldsm4(Bh[p][0], Bh[p][1], Bh[p][2], Bh[p][3],
                      bb + 2*G_AT + boff + p*16*G_ASTR + ko);
            #pragma unroll
            for (int mf = 0; mf < 4; mf++)
                #pragma unroll
                for (int nf = 0; nf < 8; nf++)
                    mma16816(acc[mf][nf], Ah[mf], &Bh[nf>>1][(nf&1)*2]);
            #pragma unroll
            for (int mf = 0; mf < 4; mf++)
                ldsm4(Al[mf][0], Al[mf][1], Al[mf][2], Al[mf][3],
                      bb + G_AT + aoff + mf*16*G_ASTR + ko);
            #pragma unroll
            for (int mf = 0; mf < 4; mf++)
                #pragma unroll
                for (int nf = 0; nf < 8; nf++)
                    mma16816(acc[mf][nf], Al[mf], &Bh[nf>>1][(nf&1)*2]);
            #pragma unroll
            for (int p = 0; p < 4; p++)
                ldsm4(Bl[p][0], Bl[p][1], Bl[p][2], Bl[p][3],
                      bb + 2*G_AT + G_BT + boff + p*16*G_ASTR + ko);
            #pragma unroll
            for (int mf = 0; mf < 4; mf++)
                #pragma unroll
                for (int nf = 0; nf < 8; nf++)
                    mma16816(acc[mf][nf], Ah[mf], &Bl[nf>>1][(nf&1)*2]);
        }
        __syncthreads();
    }

    const int tg = lane >> 2, tq = lane & 3;
    #pragma unroll
    for (int mf = 0; mf < 4; mf++) {
        const int r0 = n0 + wm*64 + mf*16 + tg;
        #pragma unroll
        for (int nf = 0; nf < 8; nf++) {
            const int c0 = d0 + wn*64 + nf*8 + tq*2;
            const float2 bv = *(const float2*)(bias + c0);
            float2 o0 = make_float2(acc[mf][nf][0] + bv.x, acc[mf][nf][1] + bv.y);
            float2 o1 = make_float2(acc[mf][nf][2] + bv.x, acc[mf][nf][3] + bv.y);
            *(float2*)(xe + (size_t)r0      * DM + c0) = o0;
            *(float2*)(xe + (size_t)(r0+8)  * DM + c0) = o1;
        }
    }
}

// ================= persistent k-means (phase A on HMMA) =================
#define XB_H   0
#define XB_L   81920
#define CB     163840
#define DS_OFF 184320
#define SM_KM  201728
#define CCH    5120

// red-arrival barrier: blocks fire red.add; block-0 monitor polls & releases
__device__ __forceinline__ void barrier_all(int inst) {
    __threadfence();
    __syncthreads();
    if (threadIdx.x == 0) {
        red_addu(&g_c1, 1);
        if (blockIdx.x == 0) {
            while (ld_acq(&g_c1) < inst * NB) { }
            st_rel(&g_r1, inst);
        } else {
            while (ld_acq(&g_r1) < inst) { }
        }
    }
    __syncthreads();
}

__global__ __launch_bounds__(256, 1) void kmeans_k(
    const float* __restrict__ xe, float* __restrict__ out)
{
    extern __shared__ char smem[];
    const uint32_t sb = smem_u32(smem);
    float* ds = (float*)(smem + DS_OFF);
    __shared__ int   sids[64];
    __shared__ int   cnts[KC];
    __shared__ int   soff[KC];
    __shared__ int   scopy[KC];
    __shared__ int   sord[64];
    __shared__ int   wtot[2];
    __shared__ float sxq[64];

    const int t    = threadIdx.x;
    const int blk  = blockIdx.x;
    const int n0   = blk * 64;
    const int lane = t & 31, w = t >> 5;
    int ab = 0;

    // ---- pre-phase: xsq, owner centsq + bf16 cent, stage xe rows as bf16 hi/lo ----
    {
        int row4 = t >> 2, part = t & 3;
        const float* xr = xe + (size_t)(n0 + row4) * DM + part * 128;
        float s = 0.f;
        #pragma unroll
        for (int q = 0; q < 32; q++) {
            float4 v = *(const float4*)(xr + q*4);
            s += v.x*v.x + v.y*v.y + v.z*v.z + v.w*v.w;
        }
        s += __shfl_xor_sync(~0u, s, 1);
        s += __shfl_xor_sync(~0u, s, 2);
        if (part == 0) sxq[row4] = s;

        if (blk < KC) {
            int e1 = blk*DM + t, e2 = e1 + 256;
            float c1 = __ldcg(&g_cent[e1]);
            float c2 = __ldcg(&g_cent[e2]);
            __nv_bfloat16 h1 = __float2bfloat16(c1);
            __nv_bfloat16 h2 = __float2bfloat16(c2);
            g_centh[e1] = h1; g_centl[e1] = __float2bfloat16(c1 - __bfloat162float(h1));
            g_centh[e2] = h2; g_centl[e2] = __float2bfloat16(c2 - __bfloat162float(h2));
            ds[t] = c1*c1 + c2*c2;
            __syncthreads();
            for (int o = 128; o; o >>= 1) { if (t < o) ds[t] += ds[t+o]; __syncthreads(); }
            if (t == 0) g_centsq[blk] = ds[0];
        }

        // convert 64 xe rows to bf16 hi/lo, chunk-major [ch][row][k32] stride 80B
        #pragma unroll
        for (int j = 0; j < 16; j++) {
            int gi = t + 256*j;
            int row = gi >> 6, grp = gi & 63;
            int ch = grp >> 2, kk = (grp & 3) * 8;
            const float* src = xe + (size_t)(n0+row)*DM + ch*32 + kk;
            float4 v0 = *(const float4*)src;
            float4 v1 = *(const float4*)(src + 4);
            float f[8] = {v0.x, v0.y, v0.z, v0.w, v1.x, v1.y, v1.z, v1.w};
            BPack ph, pl;
            #pragma unroll
            for (int q = 0; q < 8; q++) {
                __nv_bfloat16 h = __float2bfloat16(f[q]);
                ph.h[q] = h;
                pl.h[q] = __float2bfloat16(f[q] - __bfloat162float(h));
            }
            uint32_t off = ch*CCH + row*80 + kk*2;
            *(uint4*)(smem + XB_H + off) = ph.u;
            *(uint4*)(smem + XB_L + off) = pl.u;
        }
        __syncthreads();
    }
    barrier_all(++ab);

    // phase-A HMMA mapping: 8 warps = 4 m-tiles x 2 n-halves
    const int mt = w >> 1, nh = w & 1;
    const uint32_t aoff = (uint32_t)(mt*16 + (lane & 15)) * 80 + (lane >> 4) * 16;
    const uint32_t boff = (uint32_t)(nh*32 + ((lane >> 4) << 3) + (lane & 7)) * 80
                        + (((lane >> 3) & 1) * 16);
    const int tg = lane >> 2, tq = lane & 3;

    for (int it = 0; it < MAX_ITER; it++) {
        if (__ldcg(&g_done)) break;

        // ---------- PHASE A: distances via bf16x3 HMMA ----------
        {
            float acc[4][4] = {};
            const int crow = t >> 2, cseg = t & 3;

            auto stageC = [&](int ch, int slot) {
                uint32_t dst = sb + CB + slot*(2*CCH) + crow*80 + cseg*16;
                const char* srch = (const char*)g_centh + crow*1024 + ch*64 + cseg*16;
                const char* srcl = (const char*)g_centl + crow*1024 + ch*64 + cseg*16;
                cpasync_cg16(dst,       srch);
                cpasync_cg16(dst + CCH, srcl);
                CP_COMMIT();
            };

            stageC(0, 0);
            for (int ch = 0; ch < 16; ch++) {
                const int slot = ch & 1;
                const bool more = ch < 15;
                if (more) { stageC(ch + 1, slot ^ 1); CP_WAIT(1); }
                else      { CP_WAIT(0); }
                __syncthreads();

                const uint32_t xh = sb + XB_H + ch*CCH + aoff;
                const uint32_t xl = sb + XB_L + ch*CCH + aoff;
                const uint32_t bh = sb + CB + slot*(2*CCH) + boff;
                const uint32_t bl = bh + CCH;
                #pragma unroll
                for (int kh = 0; kh < 2; kh++) {
                    const uint32_t ko = kh * 32;
                    uint32_t Ah[4], Al[4], Bh[2][4], Bl[2][4];
                    ldsm4(Ah[0], Ah[1], Ah[2], Ah[3], xh + ko);
                    ldsm4(Al[0], Al[1], Al[2], Al[3], xl + ko);
                    ldsm4(Bh[0][0], Bh[0][1], Bh[0][2], Bh[0][3], bh + ko);
                    ldsm4(Bh[1][0], Bh[1][1], Bh[1][2], Bh[1][3], bh + 1280 + ko);
                    ldsm4(Bl[0][0], Bl[0][1], Bl[0][2], Bl[0][3], bl + ko);
                    ldsm4(Bl[1][0], Bl[1][1], Bl[1][2], Bl[1][3], bl + 1280 + ko);
                    #pragma unroll
                    for (int nf = 0; nf < 4; nf++) {
                        mma16816(acc[nf], Ah, &Bh[nf>>1][(nf&1)*2]);
                        mma16816(acc[nf], Ah, &Bl[nf>>1][(nf&1)*2]);
                        mma16816(acc[nf], Al, &Bh[nf>>1][(nf&1)*2]);
                    }
                }
                __syncthreads();
            }

            const int r0 = mt*16 + tg, r1 = r0 + 8;
            const float xq0 = sxq[r0], xq1 = sxq[r1];
            #pragma unroll
            for (int nf = 0; nf < 4; nf++) {
                const int c = nh*32 + nf*8 + tq*2;
                float cs0 = __ldcg(&g_centsq[c]);
                float cs1 = __ldcg(&g_centsq[c+1]);
                ds[r0*68 + c]     = xq0 - 2.f*acc[nf][0] + cs0;
                ds[r0*68 + c + 1] = xq0 - 2.f*acc[nf][1] + cs1;
                ds[r1*68 + c]     = xq1 - 2.f*acc[nf][2] + cs0;
                ds[r1*68 + c + 1] = xq1 - 2.f*acc[nf][3] + cs1;
            }
            __syncthreads();
            if (t < 64) {
                float best = 3.4e38f; int bid = 0;
                #pragma unroll 8
                for (int k = 0; k < KC; k++) {
                    float v = ds[t*68 + k];
                    if (v < best) { best = v; bid = k; }
                }
                sids[t] = bid;
            }
            __syncthreads();
        }

        // ---------- PHASE B: counting-sort rows, segment-aggregated RED ----------
        {
            if (t < KC) cnts[t] = 0;
            __syncthreads();
            if (t < 64) atomicAdd(&cnts[sids[t]], 1);
            __syncthreads();
            if (t < 64) {
                int v = cnts[t];
                int inc = v;
                #pragma unroll
                for (int o = 1; o < 32; o <<= 1) {
                    int u = __shfl_up_sync(~0u, inc, o);
                    if (lane >= o) inc += u;
                }
                soff[t] = inc - v;
                if (lane == 31) wtot[t >> 5] = inc;
            }
            __syncthreads();
            if (t >= 32 && t < 64) soff[t] += wtot[0];
            __syncthreads();
            if (t < KC) scopy[t] = soff[t];
            __syncthreads();
            if (t < 64) { int p = atomicAdd(&scopy[sids[t]], 1); sord[p] = t; }
            __syncthreads();

            const int d2 = t * 2;
            {
                int rfirst = sord[0];
                int cur = sids[rfirst];
                float2 accv = *(const float2*)(xe + (size_t)(n0+rfirst)*DM + d2);
                #pragma unroll 4
                for (int j = 1; j < 64; j++) {
                    int r = sord[j];
                    int id = sids[r];
                    float2 v = *(const float2*)(xe + (size_t)(n0+r)*DM + d2);
                    if (id != cur) {
                        float* dst = g_sums + cur*DM + d2;
                        red_addf(dst,     accv.x);
                        red_addf(dst + 1, accv.y);
                        accv = v; cur = id;
                    } else {
                        accv.x += v.x; accv.y += v.y;
                    }
                }
                float* dst = g_sums + cur*DM + d2;
                red_addf(dst,     accv.x);
                red_addf(dst + 1, accv.y);
            }
            __syncthreads();
            if (t < KC && cnts[t]) atomicAdd(&g_counts[t], cnts[t]);
        }
        barrier_all(++ab);

        // ---------- PHASE C: owners update centroids (+bf16); monitor decides ----------
        if (blk < KC) {
            const int k = blk;
            float cnt = (float)__ldcg(&g_counts[k]);
            float inv = 1.f / fmaxf(cnt, 1.f);
            bool  has = cnt > 0.f;
            float sh = 0.f, cq = 0.f;
            #pragma unroll
            for (int j = 0; j < 2; j++) {
                int e = k*DM + t + j*256;
                float old = g_cent[e];
                float nc  = has ? __ldcg(&g_sums[e]) * inv : old;
                g_cent[e] = nc;
                g_sums[e] = 0.f;
                __nv_bfloat16 h = __float2bfloat16(nc);
                g_centh[e] = h;
                g_centl[e] = __float2bfloat16(nc - __bfloat162float(h));
                float dd = nc - old;
                sh += dd*dd;
                cq += nc*nc;
            }
            ds[t] = sh; ds[256 + t] = cq;
            __syncthreads();
            for (int o = 128; o; o >>= 1) {
                if (t < o) { ds[t] += ds[t+o]; ds[256+t] += ds[256+t+o]; }
                __syncthreads();
            }
            if (t == 0) {
                g_centsq[k] = ds[256];
                atomicAdd(&g_shift, ds[0]);
                g_counts[k] = 0;
            }
        }
        // arrival + release (all blocks; block 0 monitors and decides)
        if (t == 0) {
            __threadfence();
            red_addu(&g_c2, 1);
            if (blk == 0) {
                while (ld_acq(&g_c2) < (it + 1) * NB) { }
                float tot = atomicAdd(&g_shift, 0.f);
                if (sqrtf(tot) < TOL) g_done = 1;
                g_shift = 0.f;
                __threadfence();
                st_rel(&g_r2, it + 1);
            } else {
                while (ld_acq(&g_r2) < it + 1) { }
            }
        }
        __syncthreads();
    }

    // ---------- finalize: prob one-hot + cent copy ----------
    for (int i = t; i < 1024; i += 256) {
        int row = i >> 4, kq = (i & 15) << 2;
        int id = sids[row];
        float4 o = make_float4(kq+0 == id ? 1.f : 0.f, kq+1 == id ? 1.f : 0.f,
                               kq+2 == id ? 1.f : 0.f, kq+3 == id ? 1.f : 0.f);
        *(float4*)(out + (size_t)(n0+row)*KC + kq) = o;
    }
    if (blk < KC) {
        #pragma unroll
        for (int i = t; i < 128; i += 256) {
            float4 c = *(const float4*)(g_cent + blk*DM + i*4);
            *(float4*)(out + PROB_ELEMS + blk*DM + i*4) = c;
        }
    }
}

// ================= launch =================
extern "C" void kernel_launch(void* const* d_in, const int* in_sizes, int n_in,
                              void* d_out, int out_size) {
    const float* x         = (const float*)d_in[0];
    const float* W         = (const float*)d_in[1];
    const float* bias      = (const float*)d_in[2];
    const float* centroids = (const float*)d_in[3];
    float* out = (float*)d_out;
    float* xe  = out + PROB_ELEMS + CENT_ELEMS;   // x_emb straight to output

    cudaFuncSetAttribute(mma_gemm_k, cudaFuncAttributeMaxDynamicSharedMemorySize, SM_GEMM);
    cudaFuncSetAttribute(kmeans_k,   cudaFuncAttributeMaxDynamicSharedMemorySize, SM_KM);

    prep_k<<<dim3(BS, SEQ/64), 256>>>(x, W, centroids);
    mma_gemm_k<<<dim3(DM/128, NROWS/256), 256, SM_GEMM>>>(bias, xe);
    kmeans_k<<<NB, 256, SM_KM>>>(xe, out);
}